// round 10
// baseline (speedup 1.0000x reference)
#include <cuda_runtime.h>
#include <cuda_fp16.h>
#include <math.h>
#include <stdint.h>

// ---------------------------------------------------------------------------
// Problem constants
// ---------------------------------------------------------------------------
#define BATCH 8
#define CH    192
#define HH    128
#define WW    128
#define HW    (HH*WW)            // 16384
#define TOK   (BATCH*HW)         // 131072
#define NH    8
#define HD    24
#define WS    8
#define FFN   768
#define NWIN  (BATCH*16*16)      // 2048 windows

// ---------------------------------------------------------------------------
// Scratch (device globals; no runtime allocation allowed)
// ---------------------------------------------------------------------------
__device__ __half g_xn [TOK*CH];
__device__ __half g_qkv[TOK*3*CH];
__device__ __half g_att[TOK*CH];
__device__ __half g_h1 [TOK*FFN];
__device__ float  g_x1 [TOK*CH];
__device__ float  g_gram[NH*BATCH*HD*HD];
__device__ float  g_A   [NH*BATCH*HD*HD];
// packed fp16 weights
#define W_SAQKV 0
#define W_SAPROJ (W_SAQKV + 3*CH*CH)
#define W_CAQKV (W_SAPROJ + CH*CH)
#define W_CAPROJ (W_CAQKV + 3*CH*CH)
#define W_FFN1  (W_CAPROJ + CH*CH)
#define W_FFN2  (W_FFN1 + FFN*CH)
#define W_TOTAL (W_FFN2 + CH*FFN)          // 589824
__device__ __half g_wbuf[W_TOTAL];

__device__ __forceinline__ uint32_t smem_u32(const void* p) {
    return (uint32_t)__cvta_generic_to_shared(p);
}

// ---------------------------------------------------------------------------
// Single merged fp32->fp16 conversion over all 6 weight segments
// ---------------------------------------------------------------------------
__global__ void f2h_all_kernel(const float* __restrict__ w0, const float* __restrict__ w1,
                               const float* __restrict__ w2, const float* __restrict__ w3,
                               const float* __restrict__ w4, const float* __restrict__ w5,
                               __half* __restrict__ out) {
    int i = blockIdx.x * blockDim.x + threadIdx.x;      // 4-elem chunk index
    int e = i * 4;
    if (e >= W_TOTAL) return;
    const float* src;
    int off;
    if      (e < W_SAPROJ) { src = w0; off = e - W_SAQKV; }
    else if (e < W_CAQKV)  { src = w1; off = e - W_SAPROJ; }
    else if (e < W_CAPROJ) { src = w2; off = e - W_CAQKV; }
    else if (e < W_FFN1)   { src = w3; off = e - W_CAPROJ; }
    else if (e < W_FFN2)   { src = w4; off = e - W_FFN1; }
    else                   { src = w5; off = e - W_FFN2; }
    float4 v = *(const float4*)(src + off);
    *(__half2*)(out + e)     = __floats2half2_rn(v.x, v.y);
    *(__half2*)(out + e + 2) = __floats2half2_rn(v.z, v.w);
}

// ---------------------------------------------------------------------------
// LayerNorms: fp32 in -> fp16 out
// ---------------------------------------------------------------------------
__global__ void ln_bchw_kernel(const float* __restrict__ x,
                               const float* __restrict__ w,
                               const float* __restrict__ bb,
                               __half* __restrict__ out) {
    int gwarp = (blockIdx.x * blockDim.x + threadIdx.x) >> 5;
    int lane  = threadIdx.x & 31;
    if (gwarp >= TOK) return;
    int b = gwarp >> 14;
    int l = gwarp & (HW - 1);
    const float* xp = x + ((size_t)b * CH << 14) + l;
    float v[6];
    float s = 0.f;
#pragma unroll
    for (int j = 0; j < 6; j++) {
        int c = lane + 32 * j;
        v[j] = xp[(size_t)c << 14];
        s += v[j];
    }
#pragma unroll
    for (int o = 16; o > 0; o >>= 1) s += __shfl_xor_sync(0xffffffffu, s, o);
    float mean = s * (1.f / CH);
    float s2 = 0.f;
#pragma unroll
    for (int j = 0; j < 6; j++) { float d = v[j] - mean; s2 += d * d; }
#pragma unroll
    for (int o = 16; o > 0; o >>= 1) s2 += __shfl_xor_sync(0xffffffffu, s2, o);
    float rstd = rsqrtf(s2 * (1.f / CH) + 1e-5f);
    __half* op = out + (size_t)gwarp * CH;
#pragma unroll
    for (int j = 0; j < 6; j++) {
        int c = lane + 32 * j;
        op[c] = __float2half((v[j] - mean) * rstd * w[c] + bb[c]);
    }
}

__global__ void ln_row_kernel(const float* __restrict__ x,
                              const float* __restrict__ w,
                              const float* __restrict__ bb,
                              __half* __restrict__ out) {
    int gwarp = (blockIdx.x * blockDim.x + threadIdx.x) >> 5;
    int lane  = threadIdx.x & 31;
    if (gwarp >= TOK) return;
    const float* xp = x + (size_t)gwarp * CH;
    float v[6];
    float s = 0.f;
#pragma unroll
    for (int j = 0; j < 6; j++) { v[j] = xp[lane + 32 * j]; s += v[j]; }
#pragma unroll
    for (int o = 16; o > 0; o >>= 1) s += __shfl_xor_sync(0xffffffffu, s, o);
    float mean = s * (1.f / CH);
    float s2 = 0.f;
#pragma unroll
    for (int j = 0; j < 6; j++) { float d = v[j] - mean; s2 += d * d; }
#pragma unroll
    for (int o = 16; o > 0; o >>= 1) s2 += __shfl_xor_sync(0xffffffffu, s2, o);
    float rstd = rsqrtf(s2 * (1.f / CH) + 1e-5f);
    __half* op = out + (size_t)gwarp * CH;
#pragma unroll
    for (int j = 0; j < 6; j++) {
        int c = lane + 32 * j;
        op[c] = __float2half((v[j] - mean) * rstd * w[c] + bb[c]);
    }
}

// ---------------------------------------------------------------------------
// FP16 tensor-core GEMM, m16n8k16 + cp.async 3-stage pipeline.
// C[M,N] = A[M,K] @ W[N,K]^T, fp16 in, fp32 accum.
// CTA tile 128x192x32; 12 warps (2m x 6n), warp tile 64x32 (4x4 mma tiles).
// acc = 64 regs/thread -> no spill; 12 warps/SM resident.
// Smem row = 32 halves (64B) at 80B stride: banks (20r+q) mod 32 all distinct
// per fragment load -> conflict-free without XOR swizzle.
// MODE 0: half  C = acc
// MODE 1: half  C = gelu(acc + bias)
// MODE 2: float C = resid_bchw + gamma[n]*(acc + bias)
// MODE 3: float C = resid_row  + gamma[n]*(acc + bias)  (in-place safe)
// MODE 4: float out_bchw = resid_row + gamma[n]*(acc + bias)
// ---------------------------------------------------------------------------
#define BM 128
#define BN 192
#define BK 32
#define STAGES 3
#define NTHREADS 384
#define RSTRIDE 80
#define A_ST_B (BM * RSTRIDE)             // 10240
#define B_ST_B (BN * RSTRIDE)             // 15360
#define ST_B   (A_ST_B + B_ST_B)          // 25600
#define GEMM_SMEM (STAGES * ST_B)         // 76800

__device__ __forceinline__ void cp16(uint32_t dst, const void* src) {
    asm volatile("cp.async.cg.shared.global [%0], [%1], 16;" :: "r"(dst), "l"(src) : "memory");
}

template<int MODE>
__global__ __launch_bounds__(NTHREADS, 1)
void gemm_f16_kernel(const __half* __restrict__ A, const __half* __restrict__ W,
                     void* __restrict__ CoutV, int M, int N, int K,
                     const float* __restrict__ bias,
                     const float* __restrict__ gamma,
                     const float* __restrict__ resid) {
    extern __shared__ char sm[];
    const uint32_t smBase = smem_u32(sm);

    const int n0 = blockIdx.x * BN;
    const int m0 = blockIdx.y * BM;
    const int tid  = threadIdx.x;
    const int lane = tid & 31;
    const int wid  = tid >> 5;       // 0..11
    const int wm   = wid & 1;        // 0..1 -> 64 rows each
    const int wn   = wid >> 1;       // 0..5 -> 32 cols each

    float acc[4][4][4];
#pragma unroll
    for (int i = 0; i < 4; i++)
#pragma unroll
        for (int j = 0; j < 4; j++)
#pragma unroll
            for (int q = 0; q < 4; q++) acc[i][j][q] = 0.f;

    const int nK = K / BK;

    auto load_stage = [&](int chunk, int st) {
        const int k0 = chunk * BK;
        const uint32_t aB = smBase + st * ST_B;
        const uint32_t bB = aB + A_ST_B;
        // A: 512 16B-chunks (rows 0..127, 4 chunks each)
        {
            int idx = tid;                       // 0..383
            int r = idx >> 2, c = idx & 3;
            cp16(aB + r * RSTRIDE + (c << 4), A + (size_t)(m0 + r) * K + k0 + c * 8);
            if (tid < 128) {
                idx = tid + 384;
                r = idx >> 2; c = idx & 3;
                cp16(aB + r * RSTRIDE + (c << 4), A + (size_t)(m0 + r) * K + k0 + c * 8);
            }
        }
        // B: 768 chunks (rows 0..191)
        {
            int idx = tid;
            int r = idx >> 2, c = idx & 3;
            cp16(bB + r * RSTRIDE + (c << 4), W + (size_t)(n0 + r) * K + k0 + c * 8);
            idx = tid + 384;
            r = idx >> 2; c = idx & 3;
            cp16(bB + r * RSTRIDE + (c << 4), W + (size_t)(n0 + r) * K + k0 + c * 8);
        }
        asm volatile("cp.async.commit_group;" ::: "memory");
    };

    load_stage(0, 0);
    load_stage(1, 1);

    const int fr  = lane >> 2;              // 0..7
    const uint32_t foff = (lane & 3) << 2;  // byte offset of k-quad

    int stC = 0;   // stage holding chunk kt
    for (int kt = 0; kt < nK; kt++) {
        asm volatile("cp.async.wait_group %0;" :: "n"(1) : "memory");
        __syncthreads();

        if (kt + 2 < nK) {
            int stN = stC + 2; if (stN >= STAGES) stN -= STAGES;
            load_stage(kt + 2, stN);
        } else {
            asm volatile("cp.async.commit_group;" ::: "memory");
        }

        const uint32_t aB = smBase + stC * ST_B;
        const uint32_t bB = aB + A_ST_B;

#pragma unroll
        for (int g = 0; g < 2; g++) {       // two k16 halves of BK=32
            const uint32_t gk = g * 32;
            uint32_t a[4][4];
#pragma unroll
            for (int i = 0; i < 4; i++) {
                int r0 = wm * 64 + i * 16 + fr;
                uint32_t p0 = aB + r0 * RSTRIDE + gk + foff;
                uint32_t p1 = aB + (r0 + 8) * RSTRIDE + gk + foff;
                asm volatile("ld.shared.b32 %0, [%1];" : "=r"(a[i][0]) : "r"(p0));
                asm volatile("ld.shared.b32 %0, [%1];" : "=r"(a[i][1]) : "r"(p1));
                asm volatile("ld.shared.b32 %0, [%1];" : "=r"(a[i][2]) : "r"(p0 + 16));
                asm volatile("ld.shared.b32 %0, [%1];" : "=r"(a[i][3]) : "r"(p1 + 16));
            }
            uint32_t b[4][2];
#pragma unroll
            for (int j = 0; j < 4; j++) {
                int c = wn * 32 + j * 8 + fr;
                uint32_t p = bB + c * RSTRIDE + gk + foff;
                asm volatile("ld.shared.b32 %0, [%1];" : "=r"(b[j][0]) : "r"(p));
                asm volatile("ld.shared.b32 %0, [%1];" : "=r"(b[j][1]) : "r"(p + 16));
            }
#pragma unroll
            for (int i = 0; i < 4; i++)
#pragma unroll
                for (int j = 0; j < 4; j++) {
                    asm volatile(
                        "mma.sync.aligned.m16n8k16.row.col.f32.f16.f16.f32 "
                        "{%0,%1,%2,%3},{%4,%5,%6,%7},{%8,%9},{%0,%1,%2,%3};"
                        : "+f"(acc[i][j][0]), "+f"(acc[i][j][1]),
                          "+f"(acc[i][j][2]), "+f"(acc[i][j][3])
                        : "r"(a[i][0]), "r"(a[i][1]), "r"(a[i][2]), "r"(a[i][3]),
                          "r"(b[j][0]), "r"(b[j][1]));
                }
        }
        __syncthreads();
        if (++stC == STAGES) stC = 0;
    }

    // ---- epilogue ----
    const int rq = lane >> 2;
    const int cq = (lane & 3) * 2;
    __half* Ch = (__half*)CoutV;
    float*  Cf = (float*)CoutV;
#pragma unroll
    for (int i = 0; i < 4; i++) {
#pragma unroll
        for (int j = 0; j < 4; j++) {
#pragma unroll
            for (int half_ = 0; half_ < 2; half_++) {
                int m = m0 + wm * 64 + i * 16 + rq + half_ * 8;
                int n = n0 + wn * 32 + j * 8 + cq;
                float v0 = acc[i][j][half_ * 2 + 0];
                float v1 = acc[i][j][half_ * 2 + 1];
                if (MODE == 0) {
                    *(__half2*)(Ch + (size_t)m * N + n) = __floats2half2_rn(v0, v1);
                } else if (MODE == 1) {
                    v0 += bias[n];     v1 += bias[n + 1];
                    v0 = 0.5f * v0 * (1.0f + erff(v0 * 0.70710678118654752f));
                    v1 = 0.5f * v1 * (1.0f + erff(v1 * 0.70710678118654752f));
                    *(__half2*)(Ch + (size_t)m * N + n) = __floats2half2_rn(v0, v1);
                } else if (MODE == 2) {
                    int bb_ = m >> 14, l = m & (HW - 1);
                    float r0 = resid[((size_t)(bb_ * CH + n)     << 14) + l];
                    float r1 = resid[((size_t)(bb_ * CH + n + 1) << 14) + l];
                    float2 o;
                    o.x = r0 + gamma[n]     * (v0 + bias[n]);
                    o.y = r1 + gamma[n + 1] * (v1 + bias[n + 1]);
                    *(float2*)(Cf + (size_t)m * N + n) = o;
                } else if (MODE == 3) {
                    float2 rr = *(const float2*)(resid + (size_t)m * N + n);
                    float2 o;
                    o.x = rr.x + gamma[n]     * (v0 + bias[n]);
                    o.y = rr.y + gamma[n + 1] * (v1 + bias[n + 1]);
                    *(float2*)(Cf + (size_t)m * N + n) = o;
                } else { // MODE 4
                    int bb_ = m >> 14, l = m & (HW - 1);
                    float r0 = resid[(size_t)m * N + n];
                    float r1 = resid[(size_t)m * N + n + 1];
                    Cf[((size_t)(bb_ * CH + n)     << 14) + l] = r0 + gamma[n]     * (v0 + bias[n]);
                    Cf[((size_t)(bb_ * CH + n + 1) << 14) + l] = r1 + gamma[n + 1] * (v1 + bias[n + 1]);
                }
            }
        }
    }
}

// ---------------------------------------------------------------------------
// Window attention (fp16 qkv in/out, fp32 math)
// ---------------------------------------------------------------------------
__global__ __launch_bounds__(64)
void win_attn_kernel(const __half* __restrict__ qkv,
                     const float* __restrict__ table,
                     __half* __restrict__ out) {
    int h   = blockIdx.x & 7;
    int wid = blockIdx.x >> 3;
    int b   = wid >> 8;
    int rem = wid & 255;
    int wy  = rem >> 4, wx = rem & 15;

    int i  = threadIdx.x;
    int iy = i >> 3, ix = i & 7;
    int t  = (b << 14) + ((wy * 8 + iy) << 7) + wx * 8 + ix;

    __shared__ float ks[64][24];
    __shared__ float vs[64][24];
    __shared__ float bt[225];
    for (int p = i; p < 225; p += 64) bt[p] = table[p * NH + h];

    const __half* row = qkv + (size_t)t * (3 * CH) + h * HD;
    float q[24];
#pragma unroll
    for (int d = 0; d < HD; d++) {
        q[d]     = __half2float(row[d]);
        ks[i][d] = __half2float(row[CH + d]);
        vs[i][d] = __half2float(row[2 * CH + d]);
    }
    __syncthreads();

    const float scale = 0.20412414523193154f;
    float sc[64];
    float mx = -1e30f;
#pragma unroll 4
    for (int j = 0; j < 64; j++) {
        int jy = j >> 3, jx = j & 7;
        float dot = 0.f;
#pragma unroll
        for (int d = 0; d < HD; d++) dot += q[d] * ks[j][d];
        dot = dot * scale + bt[(iy - jy + 7) * 15 + (ix - jx + 7)];
        sc[j] = dot;
        mx = fmaxf(mx, dot);
    }
    float sum = 0.f;
#pragma unroll 4
    for (int j = 0; j < 64; j++) { sc[j] = __expf(sc[j] - mx); sum += sc[j]; }
    float inv = 1.f / sum;

    float accum[24];
#pragma unroll
    for (int d = 0; d < HD; d++) accum[d] = 0.f;
#pragma unroll 2
    for (int j = 0; j < 64; j++) {
        float p = sc[j];
#pragma unroll
        for (int d = 0; d < HD; d++) accum[d] += p * vs[j][d];
    }
    __half* op = out + (size_t)t * CH + h * HD;
#pragma unroll
    for (int d = 0; d < HD; d++) op[d] = __float2half(accum[d] * inv);
}

// ---------------------------------------------------------------------------
// Channel attention
// ---------------------------------------------------------------------------
__global__ __launch_bounds__(576)
void ca_gram_kernel(const __half* __restrict__ qkv, float* __restrict__ gram) {
    int bh = blockIdx.x;
    int b = bh >> 3, h = bh & 7;
    int tid = threadIdx.x;
    int d = tid / 24, e = tid - d * 24;

    __shared__ float qs[64][24];
    __shared__ float ks[64][24];

    const int chunk = HW / 16;
    int l0 = blockIdx.y * chunk;
    float accum = 0.f;
    for (int tile = 0; tile < chunk; tile += 64) {
        for (int p = tid; p < 64 * 24; p += 576) {
            int tok = p / 24, dd = p - tok * 24;
            size_t base = (size_t)((b << 14) + l0 + tile + tok) * (3 * CH) + h * HD + dd;
            qs[tok][dd] = __half2float(qkv[base]);
            ks[tok][dd] = __half2float(qkv[base + CH]);
        }
        __syncthreads();
#pragma unroll 8
        for (int tok = 0; tok < 64; tok++) accum += qs[tok][d] * ks[tok][e];
        __syncthreads();
    }
    atomicAdd(&gram[bh * (HD * HD) + tid], accum);
}

__global__ void zero_gram_kernel(float* __restrict__ gram) {
    int i = blockIdx.x * blockDim.x + threadIdx.x;
    if (i < NH * BATCH * HD * HD) gram[i] = 0.f;
}

__global__ void ca_softmax_kernel(const float* __restrict__ gram, float* __restrict__ A) {
    int bh = blockIdx.x;
    int d = threadIdx.x;
    if (d >= HD) return;
    const float scale = 0.20412414523193154f;
    float r[24];
    float mx = -1e30f;
#pragma unroll
    for (int e = 0; e < HD; e++) {
        r[e] = gram[bh * (HD * HD) + d * HD + e] * scale;
        mx = fmaxf(mx, r[e]);
    }
    float sum = 0.f;
#pragma unroll
    for (int e = 0; e < HD; e++) { r[e] = __expf(r[e] - mx); sum += r[e]; }
    float inv = 1.f / sum;
#pragma unroll
    for (int e = 0; e < HD; e++) A[bh * (HD * HD) + d * HD + e] = r[e] * inv;
}

__global__ __launch_bounds__(256)
void ca_out_kernel(const __half* __restrict__ qkv, const float* __restrict__ A,
                   __half* __restrict__ out) {
    int b  = blockIdx.x;
    int l0 = blockIdx.y * 32;
    int tid = threadIdx.x;
    __shared__ float vs[32][192];
    for (int p = tid; p < 32 * 192; p += 256) {
        int tok = p / 192, c = p - tok * 192;
        vs[tok][c] = __half2float(qkv[(size_t)((b << 14) + l0 + tok) * (3 * CH) + 2 * CH + c]);
    }
    __syncthreads();
    int tok = tid >> 3;
    int h   = tid & 7;
    int t   = (b << 14) + l0 + tok;
    const float* Ah = A + (b * 8 + h) * (HD * HD);
    __half* op = out + (size_t)t * CH + h * HD;
#pragma unroll
    for (int d = 0; d < HD; d++) {
        float s = 0.f;
#pragma unroll
        for (int e = 0; e < HD; e++) s += Ah[d * HD + e] * vs[tok][h * HD + e];
        op[d] = __float2half(s);
    }
}

// ---------------------------------------------------------------------------
// Launch
// ---------------------------------------------------------------------------
extern "C" void kernel_launch(void* const* d_in, const int* in_sizes, int n_in,
                              void* d_out, int out_size) {
    const float* x          = (const float*)d_in[0];
    const float* sa_norm_w  = (const float*)d_in[1];
    const float* sa_norm_b  = (const float*)d_in[2];
    const float* sa_qkv_w   = (const float*)d_in[3];
    const float* sa_proj_w  = (const float*)d_in[4];
    const float* sa_proj_b  = (const float*)d_in[5];
    const float* sa_bias_t  = (const float*)d_in[6];
    const float* ca_norm_w  = (const float*)d_in[7];
    const float* ca_norm_b  = (const float*)d_in[8];
    const float* ca_qkv_w   = (const float*)d_in[9];
    const float* ca_proj_w  = (const float*)d_in[10];
    const float* ca_proj_b  = (const float*)d_in[11];
    const float* ffn_norm_w = (const float*)d_in[12];
    const float* ffn_norm_b = (const float*)d_in[13];
    const float* ffn_w1     = (const float*)d_in[14];
    const float* ffn_b1     = (const float*)d_in[15];
    const float* ffn_w2     = (const float*)d_in[16];
    const float* ffn_w2b    = (const float*)d_in[17];
    const float* gamma1     = (const float*)d_in[18];
    const float* gamma2     = (const float*)d_in[19];
    const float* gamma3     = (const float*)d_in[20];
    float* out = (float*)d_out;

    __half *xn, *qkv, *att, *h1, *wbuf;
    float *x1, *gram, *Amat;
    cudaGetSymbolAddress((void**)&xn,   g_xn);
    cudaGetSymbolAddress((void**)&qkv,  g_qkv);
    cudaGetSymbolAddress((void**)&att,  g_att);
    cudaGetSymbolAddress((void**)&h1,   g_h1);
    cudaGetSymbolAddress((void**)&x1,   g_x1);
    cudaGetSymbolAddress((void**)&gram, g_gram);
    cudaGetSymbolAddress((void**)&Amat, g_A);
    cudaGetSymbolAddress((void**)&wbuf, g_wbuf);

    const int smemB = GEMM_SMEM;  // 76800
    cudaFuncSetAttribute(gemm_f16_kernel<0>, cudaFuncAttributeMaxDynamicSharedMemorySize, smemB);
    cudaFuncSetAttribute(gemm_f16_kernel<1>, cudaFuncAttributeMaxDynamicSharedMemorySize, smemB);
    cudaFuncSetAttribute(gemm_f16_kernel<2>, cudaFuncAttributeMaxDynamicSharedMemorySize, smemB);
    cudaFuncSetAttribute(gemm_f16_kernel<3>, cudaFuncAttributeMaxDynamicSharedMemorySize, smemB);
    cudaFuncSetAttribute(gemm_f16_kernel<4>, cudaFuncAttributeMaxDynamicSharedMemorySize, smemB);

    f2h_all_kernel<<<(W_TOTAL / 4 + 255) / 256, 256>>>(
        sa_qkv_w, sa_proj_w, ca_qkv_w, ca_proj_w, ffn_w1, ffn_w2, wbuf);

    const int lnBlocks = TOK / 8;

    // ---- stage 1: window attention ----
    ln_bchw_kernel<<<lnBlocks, 256>>>(x, sa_norm_w, sa_norm_b, xn);
    gemm_f16_kernel<0><<<dim3(3 * CH / BN, TOK / BM), NTHREADS, smemB>>>(
        xn, wbuf + W_SAQKV, qkv, TOK, 3 * CH, CH, nullptr, nullptr, nullptr);
    win_attn_kernel<<<NWIN * NH, 64>>>(qkv, sa_bias_t, att);
    gemm_f16_kernel<2><<<dim3(CH / BN, TOK / BM), NTHREADS, smemB>>>(
        att, wbuf + W_SAPROJ, x1, TOK, CH, CH, sa_proj_b, gamma1, x);

    // ---- stage 2: channel attention ----
    ln_row_kernel<<<lnBlocks, 256>>>(x1, ca_norm_w, ca_norm_b, xn);
    gemm_f16_kernel<0><<<dim3(3 * CH / BN, TOK / BM), NTHREADS, smemB>>>(
        xn, wbuf + W_CAQKV, qkv, TOK, 3 * CH, CH, nullptr, nullptr, nullptr);
    zero_gram_kernel<<<(NH * BATCH * HD * HD + 255) / 256, 256>>>(gram);
    ca_gram_kernel<<<dim3(NH * BATCH, 16), 576>>>(qkv, gram);
    ca_softmax_kernel<<<NH * BATCH, 32>>>(gram, Amat);
    ca_out_kernel<<<dim3(BATCH, HW / 32), 256>>>(qkv, Amat, att);
    gemm_f16_kernel<3><<<dim3(CH / BN, TOK / BM), NTHREADS, smemB>>>(
        att, wbuf + W_CAPROJ, x1, TOK, CH, CH, ca_proj_b, gamma2, x1);

    // ---- stage 3: gated FFN ----
    ln_row_kernel<<<lnBlocks, 256>>>(x1, ffn_norm_w, ffn_norm_b, xn);
    gemm_f16_kernel<1><<<dim3(FFN / BN, TOK / BM), NTHREADS, smemB>>>(
        xn, wbuf + W_FFN1, h1, TOK, FFN, CH, ffn_b1, nullptr, nullptr);
    gemm_f16_kernel<4><<<dim3(CH / BN, TOK / BM), NTHREADS, smemB>>>(
        h1, wbuf + W_FFN2, out, TOK, CH, FFN, ffn_w2b, gamma3, x1);
}

// round 12
// speedup vs baseline: 1.2617x; 1.2617x over previous
#include <cuda_runtime.h>
#include <cuda_fp16.h>
#include <math.h>
#include <stdint.h>

// ---------------------------------------------------------------------------
// Problem constants
// ---------------------------------------------------------------------------
#define BATCH 8
#define CH    192
#define HH    128
#define WW    128
#define HW    (HH*WW)            // 16384
#define TOK   (BATCH*HW)         // 131072
#define NH    8
#define HD    24
#define WS    8
#define FFN   768
#define NWIN  (BATCH*16*16)      // 2048 windows

// ---------------------------------------------------------------------------
// Scratch (device globals; no runtime allocation allowed)
// ---------------------------------------------------------------------------
__device__ __half g_xn [TOK*CH];
__device__ __half g_qkv[TOK*3*CH];
__device__ __half g_att[TOK*CH];
__device__ __half g_h1 [TOK*FFN];
__device__ float  g_x1 [TOK*CH];
__device__ float  g_gram[NH*BATCH*HD*HD];
__device__ float  g_A   [NH*BATCH*HD*HD];
// packed fp16 weights
#define W_SAQKV 0
#define W_SAPROJ (W_SAQKV + 3*CH*CH)
#define W_CAQKV (W_SAPROJ + CH*CH)
#define W_CAPROJ (W_CAQKV + 3*CH*CH)
#define W_FFN1  (W_CAPROJ + CH*CH)
#define W_FFN2  (W_FFN1 + FFN*CH)
#define W_TOTAL (W_FFN2 + CH*FFN)          // 589824
__device__ __half g_wbuf[W_TOTAL];

__device__ __forceinline__ uint32_t smem_u32(const void* p) {
    return (uint32_t)__cvta_generic_to_shared(p);
}

// ---------------------------------------------------------------------------
// Single merged fp32->fp16 conversion over all 6 weight segments
// ---------------------------------------------------------------------------
__global__ void f2h_all_kernel(const float* __restrict__ w0, const float* __restrict__ w1,
                               const float* __restrict__ w2, const float* __restrict__ w3,
                               const float* __restrict__ w4, const float* __restrict__ w5,
                               __half* __restrict__ out) {
    int i = blockIdx.x * blockDim.x + threadIdx.x;
    int e = i * 4;
    if (e >= W_TOTAL) return;
    const float* src;
    int off;
    if      (e < W_SAPROJ) { src = w0; off = e - W_SAQKV; }
    else if (e < W_CAQKV)  { src = w1; off = e - W_SAPROJ; }
    else if (e < W_CAPROJ) { src = w2; off = e - W_CAQKV; }
    else if (e < W_FFN1)   { src = w3; off = e - W_CAPROJ; }
    else if (e < W_FFN2)   { src = w4; off = e - W_FFN1; }
    else                   { src = w5; off = e - W_FFN2; }
    float4 v = *(const float4*)(src + off);
    *(__half2*)(out + e)     = __floats2half2_rn(v.x, v.y);
    *(__half2*)(out + e + 2) = __floats2half2_rn(v.z, v.w);
}

// ---------------------------------------------------------------------------
// LayerNorms: fp32 in -> fp16 out
// ---------------------------------------------------------------------------
__global__ void ln_bchw_kernel(const float* __restrict__ x,
                               const float* __restrict__ w,
                               const float* __restrict__ bb,
                               __half* __restrict__ out) {
    int gwarp = (blockIdx.x * blockDim.x + threadIdx.x) >> 5;
    int lane  = threadIdx.x & 31;
    if (gwarp >= TOK) return;
    int b = gwarp >> 14;
    int l = gwarp & (HW - 1);
    const float* xp = x + ((size_t)b * CH << 14) + l;
    float v[6];
    float s = 0.f;
#pragma unroll
    for (int j = 0; j < 6; j++) {
        int c = lane + 32 * j;
        v[j] = xp[(size_t)c << 14];
        s += v[j];
    }
#pragma unroll
    for (int o = 16; o > 0; o >>= 1) s += __shfl_xor_sync(0xffffffffu, s, o);
    float mean = s * (1.f / CH);
    float s2 = 0.f;
#pragma unroll
    for (int j = 0; j < 6; j++) { float d = v[j] - mean; s2 += d * d; }
#pragma unroll
    for (int o = 16; o > 0; o >>= 1) s2 += __shfl_xor_sync(0xffffffffu, s2, o);
    float rstd = rsqrtf(s2 * (1.f / CH) + 1e-5f);
    __half* op = out + (size_t)gwarp * CH;
#pragma unroll
    for (int j = 0; j < 6; j++) {
        int c = lane + 32 * j;
        op[c] = __float2half((v[j] - mean) * rstd * w[c] + bb[c]);
    }
}

__global__ void ln_row_kernel(const float* __restrict__ x,
                              const float* __restrict__ w,
                              const float* __restrict__ bb,
                              __half* __restrict__ out) {
    int gwarp = (blockIdx.x * blockDim.x + threadIdx.x) >> 5;
    int lane  = threadIdx.x & 31;
    if (gwarp >= TOK) return;
    const float* xp = x + (size_t)gwarp * CH;
    float v[6];
    float s = 0.f;
#pragma unroll
    for (int j = 0; j < 6; j++) { v[j] = xp[lane + 32 * j]; s += v[j]; }
#pragma unroll
    for (int o = 16; o > 0; o >>= 1) s += __shfl_xor_sync(0xffffffffu, s, o);
    float mean = s * (1.f / CH);
    float s2 = 0.f;
#pragma unroll
    for (int j = 0; j < 6; j++) { float d = v[j] - mean; s2 += d * d; }
#pragma unroll
    for (int o = 16; o > 0; o >>= 1) s2 += __shfl_xor_sync(0xffffffffu, s2, o);
    float rstd = rsqrtf(s2 * (1.f / CH) + 1e-5f);
    __half* op = out + (size_t)gwarp * CH;
#pragma unroll
    for (int j = 0; j < 6; j++) {
        int c = lane + 32 * j;
        op[c] = __float2half((v[j] - mean) * rstd * w[c] + bb[c]);
    }
}

// ---------------------------------------------------------------------------
// FP16 tensor-core GEMM (R9 config: 128x96x32, 8 warps, 4-stage cp.async)
// ---------------------------------------------------------------------------
#define BM 128
#define BN 96
#define BK 32
#define STAGES 4
#define RSTRIDE 80
#define A_ST_B (BM * RSTRIDE)             // 10240
#define B_ST_B (BN * RSTRIDE)             // 7680
#define ST_B   (A_ST_B + B_ST_B)          // 17920
#define GEMM_SMEM (STAGES * ST_B)         // 71680

__device__ __forceinline__ void cp16(uint32_t dst, const void* src) {
    asm volatile("cp.async.cg.shared.global [%0], [%1], 16;" :: "r"(dst), "l"(src) : "memory");
}

template<int MODE>
__global__ __launch_bounds__(256, 2)
void gemm_f16_kernel(const __half* __restrict__ A, const __half* __restrict__ W,
                     void* __restrict__ CoutV, int M, int N, int K,
                     const float* __restrict__ bias,
                     const float* __restrict__ gamma,
                     const float* __restrict__ resid) {
    extern __shared__ char sm[];
    const uint32_t smBase = smem_u32(sm);

    const int n0 = blockIdx.x * BN;
    const int m0 = blockIdx.y * BM;
    const int tid  = threadIdx.x;
    const int lane = tid & 31;
    const int wid  = tid >> 5;
    const int wm   = wid & 3;
    const int wn   = wid >> 2;

    float acc[2][6][4];
#pragma unroll
    for (int i = 0; i < 2; i++)
#pragma unroll
        for (int j = 0; j < 6; j++)
#pragma unroll
            for (int q = 0; q < 4; q++) acc[i][j][q] = 0.f;

    const int nK = K / BK;

    const int ldRow = tid >> 2;
    const int ldC   = tid & 3;

    auto load_stage = [&](int chunk, int st) {
        const int k0 = chunk * BK;
        const uint32_t aB = smBase + st * ST_B;
        const uint32_t bB = aB + A_ST_B;
#pragma unroll
        for (int it = 0; it < 2; it++) {
            int r = ldRow + it * 64;
            cp16(aB + r * RSTRIDE + (ldC << 4), A + (size_t)(m0 + r) * K + k0 + ldC * 8);
        }
        {
            int r = ldRow;
            cp16(bB + r * RSTRIDE + (ldC << 4), W + (size_t)(n0 + r) * K + k0 + ldC * 8);
        }
        if (tid < 128) {
            int r = 64 + ldRow;
            cp16(bB + r * RSTRIDE + (ldC << 4), W + (size_t)(n0 + r) * K + k0 + ldC * 8);
        }
        asm volatile("cp.async.commit_group;" ::: "memory");
    };

    load_stage(0, 0);
    load_stage(1, 1);
    load_stage(2, 2);

    const int fr  = lane >> 2;
    const uint32_t foff = (lane & 3) << 2;

    for (int kt = 0; kt < nK; kt++) {
        asm volatile("cp.async.wait_group %0;" :: "n"(STAGES - 2) : "memory");
        __syncthreads();

        if (kt + STAGES - 1 < nK) load_stage(kt + STAGES - 1, (kt + STAGES - 1) & (STAGES - 1));
        else asm volatile("cp.async.commit_group;" ::: "memory");

        const int st = kt & (STAGES - 1);
        const uint32_t aB = smBase + st * ST_B;
        const uint32_t bB = aB + A_ST_B;

#pragma unroll
        for (int g = 0; g < 2; g++) {
            const uint32_t gk = g * 32;
            uint32_t a[2][4];
#pragma unroll
            for (int i = 0; i < 2; i++) {
                int r0 = wm * 32 + i * 16 + fr;
                int r1 = r0 + 8;
                uint32_t p0 = aB + r0 * RSTRIDE + gk + foff;
                uint32_t p1 = aB + r1 * RSTRIDE + gk + foff;
                asm volatile("ld.shared.b32 %0, [%1];" : "=r"(a[i][0]) : "r"(p0));
                asm volatile("ld.shared.b32 %0, [%1];" : "=r"(a[i][1]) : "r"(p1));
                asm volatile("ld.shared.b32 %0, [%1];" : "=r"(a[i][2]) : "r"(p0 + 16));
                asm volatile("ld.shared.b32 %0, [%1];" : "=r"(a[i][3]) : "r"(p1 + 16));
            }
            uint32_t b[6][2];
#pragma unroll
            for (int j = 0; j < 6; j++) {
                int c = wn * 48 + j * 8 + fr;
                uint32_t p = bB + c * RSTRIDE + gk + foff;
                asm volatile("ld.shared.b32 %0, [%1];" : "=r"(b[j][0]) : "r"(p));
                asm volatile("ld.shared.b32 %0, [%1];" : "=r"(b[j][1]) : "r"(p + 16));
            }
#pragma unroll
            for (int i = 0; i < 2; i++)
#pragma unroll
                for (int j = 0; j < 6; j++) {
                    asm volatile(
                        "mma.sync.aligned.m16n8k16.row.col.f32.f16.f16.f32 "
                        "{%0,%1,%2,%3},{%4,%5,%6,%7},{%8,%9},{%0,%1,%2,%3};"
                        : "+f"(acc[i][j][0]), "+f"(acc[i][j][1]),
                          "+f"(acc[i][j][2]), "+f"(acc[i][j][3])
                        : "r"(a[i][0]), "r"(a[i][1]), "r"(a[i][2]), "r"(a[i][3]),
                          "r"(b[j][0]), "r"(b[j][1]));
                }
        }
        __syncthreads();
    }

    // ---- epilogue ----
    const int rq = lane >> 2;
    const int cq = (lane & 3) * 2;
    __half* Ch = (__half*)CoutV;
    float*  Cf = (float*)CoutV;
#pragma unroll
    for (int i = 0; i < 2; i++) {
#pragma unroll
        for (int j = 0; j < 6; j++) {
#pragma unroll
            for (int half_ = 0; half_ < 2; half_++) {
                int m = m0 + wm * 32 + i * 16 + rq + half_ * 8;
                int n = n0 + wn * 48 + j * 8 + cq;
                float v0 = acc[i][j][half_ * 2 + 0];
                float v1 = acc[i][j][half_ * 2 + 1];
                if (MODE == 0) {
                    *(__half2*)(Ch + (size_t)m * N + n) = __floats2half2_rn(v0, v1);
                } else if (MODE == 1) {
                    v0 += bias[n];     v1 += bias[n + 1];
                    v0 = 0.5f * v0 * (1.0f + erff(v0 * 0.70710678118654752f));
                    v1 = 0.5f * v1 * (1.0f + erff(v1 * 0.70710678118654752f));
                    *(__half2*)(Ch + (size_t)m * N + n) = __floats2half2_rn(v0, v1);
                } else if (MODE == 2) {
                    int bb_ = m >> 14, l = m & (HW - 1);
                    float r0 = resid[((size_t)(bb_ * CH + n)     << 14) + l];
                    float r1 = resid[((size_t)(bb_ * CH + n + 1) << 14) + l];
                    float2 o;
                    o.x = r0 + gamma[n]     * (v0 + bias[n]);
                    o.y = r1 + gamma[n + 1] * (v1 + bias[n + 1]);
                    *(float2*)(Cf + (size_t)m * N + n) = o;
                } else if (MODE == 3) {
                    float2 rr = *(const float2*)(resid + (size_t)m * N + n);
                    float2 o;
                    o.x = rr.x + gamma[n]     * (v0 + bias[n]);
                    o.y = rr.y + gamma[n + 1] * (v1 + bias[n + 1]);
                    *(float2*)(Cf + (size_t)m * N + n) = o;
                } else { // MODE 4
                    int bb_ = m >> 14, l = m & (HW - 1);
                    float r0 = resid[(size_t)m * N + n];
                    float r1 = resid[(size_t)m * N + n + 1];
                    Cf[((size_t)(bb_ * CH + n)     << 14) + l] = r0 + gamma[n]     * (v0 + bias[n]);
                    Cf[((size_t)(bb_ * CH + n + 1) << 14) + l] = r1 + gamma[n + 1] * (v1 + bias[n + 1]);
                }
            }
        }
    }
}

// ---------------------------------------------------------------------------
// Window attention v2: online softmax (no sc[] spill), float4 smem reads,
// uint4 vector global loads. One block = (window, head), 64 threads.
// ---------------------------------------------------------------------------
__global__ __launch_bounds__(64)
void win_attn_kernel(const __half* __restrict__ qkv,
                     const float* __restrict__ table,
                     __half* __restrict__ out) {
    int h   = blockIdx.x & 7;
    int wid = blockIdx.x >> 3;
    int b   = wid >> 8;
    int rem = wid & 255;
    int wy  = rem >> 4, wx = rem & 15;

    int i  = threadIdx.x;
    int iy = i >> 3, ix = i & 7;
    int t  = (b << 14) + ((wy * 8 + iy) << 7) + wx * 8 + ix;

    __shared__ float ks[64][24];   // row = 96B, 16B aligned
    __shared__ float vs[64][24];
    __shared__ float bt[240];
    for (int p = i; p < 225; p += 64) bt[p] = table[p * NH + h];

    // vectorized global loads: q/k/v rows are 24 halves = 3 x uint4 each
    const uint4* rowp = (const uint4*)(qkv + (size_t)t * (3 * CH) + h * HD);
    float q[24];
#pragma unroll
    for (int c4 = 0; c4 < 3; c4++) {
        uint4 qv = rowp[c4];
        uint4 kv = rowp[c4 + CH / 8];       // +192 halves
        uint4 vv = rowp[c4 + 2 * CH / 8];   // +384 halves
        const __half2* qh = (const __half2*)&qv;
        const __half2* kh = (const __half2*)&kv;
        const __half2* vh = (const __half2*)&vv;
#pragma unroll
        for (int p = 0; p < 4; p++) {
            float2 qf = __half22float2(qh[p]);
            float2 kf = __half22float2(kh[p]);
            float2 vf = __half22float2(vh[p]);
            q[c4 * 8 + p * 2]     = qf.x;
            q[c4 * 8 + p * 2 + 1] = qf.y;
            ks[i][c4 * 8 + p * 2]     = kf.x;
            ks[i][c4 * 8 + p * 2 + 1] = kf.y;
            vs[i][c4 * 8 + p * 2]     = vf.x;
            vs[i][c4 * 8 + p * 2 + 1] = vf.y;
        }
    }
    __syncthreads();

    const float scale = 0.20412414523193154f; // 1/sqrt(24)
    float mx = -1e30f;
    float sum = 0.f;
    float accum[24];
#pragma unroll
    for (int d = 0; d < HD; d++) accum[d] = 0.f;

#pragma unroll 2
    for (int j = 0; j < 64; j++) {
        int jy = j >> 3, jx = j & 7;
        const float4* kr = (const float4*)&ks[j][0];
        float4 k0 = kr[0], k1 = kr[1], k2 = kr[2], k3 = kr[3], k4 = kr[4], k5 = kr[5];
        float dot =
            q[0]*k0.x + q[1]*k0.y + q[2]*k0.z + q[3]*k0.w +
            q[4]*k1.x + q[5]*k1.y + q[6]*k1.z + q[7]*k1.w +
            q[8]*k2.x + q[9]*k2.y + q[10]*k2.z + q[11]*k2.w +
            q[12]*k3.x + q[13]*k3.y + q[14]*k3.z + q[15]*k3.w +
            q[16]*k4.x + q[17]*k4.y + q[18]*k4.z + q[19]*k4.w +
            q[20]*k5.x + q[21]*k5.y + q[22]*k5.z + q[23]*k5.w;
        dot = dot * scale + bt[(iy - jy + 7) * 15 + (ix - jx + 7)];

        if (dot > mx) {   // rare: rescale running state
            float rs = __expf(mx - dot);
            sum *= rs;
#pragma unroll
            for (int d = 0; d < HD; d++) accum[d] *= rs;
            mx = dot;
        }
        float p = __expf(dot - mx);
        sum += p;
        const float4* vr = (const float4*)&vs[j][0];
        float4 v0 = vr[0], v1 = vr[1], v2 = vr[2], v3 = vr[3], v4 = vr[4], v5 = vr[5];
        accum[0]  += p * v0.x;  accum[1]  += p * v0.y;  accum[2]  += p * v0.z;  accum[3]  += p * v0.w;
        accum[4]  += p * v1.x;  accum[5]  += p * v1.y;  accum[6]  += p * v1.z;  accum[7]  += p * v1.w;
        accum[8]  += p * v2.x;  accum[9]  += p * v2.y;  accum[10] += p * v2.z;  accum[11] += p * v2.w;
        accum[12] += p * v3.x;  accum[13] += p * v3.y;  accum[14] += p * v3.z;  accum[15] += p * v3.w;
        accum[16] += p * v4.x;  accum[17] += p * v4.y;  accum[18] += p * v4.z;  accum[19] += p * v4.w;
        accum[20] += p * v5.x;  accum[21] += p * v5.y;  accum[22] += p * v5.z;  accum[23] += p * v5.w;
    }
    float inv = 1.f / sum;

    __half* op = out + (size_t)t * CH + h * HD;
    uint4 ov[3];
    __half2* oh = (__half2*)ov;
#pragma unroll
    for (int p = 0; p < 12; p++)
        oh[p] = __floats2half2_rn(accum[p * 2] * inv, accum[p * 2 + 1] * inv);
    uint4* op4 = (uint4*)op;
#pragma unroll
    for (int c4 = 0; c4 < 3; c4++) op4[c4] = ov[c4];
}

// ---------------------------------------------------------------------------
// Channel attention
// ---------------------------------------------------------------------------
__global__ __launch_bounds__(576)
void ca_gram_kernel(const __half* __restrict__ qkv, float* __restrict__ gram) {
    int bh = blockIdx.x;
    int b = bh >> 3, h = bh & 7;
    int tid = threadIdx.x;
    int d = tid / 24, e = tid - d * 24;

    __shared__ float qs[64][24];
    __shared__ float ks[64][24];

    const int chunk = HW / 16;
    int l0 = blockIdx.y * chunk;
    float accum = 0.f;
    for (int tile = 0; tile < chunk; tile += 64) {
        for (int p = tid; p < 64 * 24; p += 576) {
            int tok = p / 24, dd = p - tok * 24;
            size_t base = (size_t)((b << 14) + l0 + tile + tok) * (3 * CH) + h * HD + dd;
            qs[tok][dd] = __half2float(qkv[base]);
            ks[tok][dd] = __half2float(qkv[base + CH]);
        }
        __syncthreads();
#pragma unroll 8
        for (int tok = 0; tok < 64; tok++) accum += qs[tok][d] * ks[tok][e];
        __syncthreads();
    }
    atomicAdd(&gram[bh * (HD * HD) + tid], accum);
}

__global__ void zero_gram_kernel(float* __restrict__ gram) {
    int i = blockIdx.x * blockDim.x + threadIdx.x;
    if (i < NH * BATCH * HD * HD) gram[i] = 0.f;
}

__global__ void ca_softmax_kernel(const float* __restrict__ gram, float* __restrict__ A) {
    int bh = blockIdx.x;
    int d = threadIdx.x;
    if (d >= HD) return;
    const float scale = 0.20412414523193154f;
    float r[24];
    float mx = -1e30f;
#pragma unroll
    for (int e = 0; e < HD; e++) {
        r[e] = gram[bh * (HD * HD) + d * HD + e] * scale;
        mx = fmaxf(mx, r[e]);
    }
    float sum = 0.f;
#pragma unroll
    for (int e = 0; e < HD; e++) { r[e] = __expf(r[e] - mx); sum += r[e]; }
    float inv = 1.f / sum;
#pragma unroll
    for (int e = 0; e < HD; e++) A[bh * (HD * HD) + d * HD + e] = r[e] * inv;
}

__global__ __launch_bounds__(256)
void ca_out_kernel(const __half* __restrict__ qkv, const float* __restrict__ A,
                   __half* __restrict__ out) {
    int b  = blockIdx.x;
    int l0 = blockIdx.y * 32;
    int tid = threadIdx.x;
    __shared__ float vs[32][192];
    for (int p = tid; p < 32 * 192; p += 256) {
        int tok = p / 192, c = p - tok * 192;
        vs[tok][c] = __half2float(qkv[(size_t)((b << 14) + l0 + tok) * (3 * CH) + 2 * CH + c]);
    }
    __syncthreads();
    int tok = tid >> 3;
    int h   = tid & 7;
    int t   = (b << 14) + l0 + tok;
    const float* Ah = A + (b * 8 + h) * (HD * HD);
    __half* op = out + (size_t)t * CH + h * HD;
#pragma unroll
    for (int d = 0; d < HD; d++) {
        float s = 0.f;
#pragma unroll
        for (int e = 0; e < HD; e++) s += Ah[d * HD + e] * vs[tok][h * HD + e];
        op[d] = __float2half(s);
    }
}

// ---------------------------------------------------------------------------
// Launch
// ---------------------------------------------------------------------------
extern "C" void kernel_launch(void* const* d_in, const int* in_sizes, int n_in,
                              void* d_out, int out_size) {
    const float* x          = (const float*)d_in[0];
    const float* sa_norm_w  = (const float*)d_in[1];
    const float* sa_norm_b  = (const float*)d_in[2];
    const float* sa_qkv_w   = (const float*)d_in[3];
    const float* sa_proj_w  = (const float*)d_in[4];
    const float* sa_proj_b  = (const float*)d_in[5];
    const float* sa_bias_t  = (const float*)d_in[6];
    const float* ca_norm_w  = (const float*)d_in[7];
    const float* ca_norm_b  = (const float*)d_in[8];
    const float* ca_qkv_w   = (const float*)d_in[9];
    const float* ca_proj_w  = (const float*)d_in[10];
    const float* ca_proj_b  = (const float*)d_in[11];
    const float* ffn_norm_w = (const float*)d_in[12];
    const float* ffn_norm_b = (const float*)d_in[13];
    const float* ffn_w1     = (const float*)d_in[14];
    const float* ffn_b1     = (const float*)d_in[15];
    const float* ffn_w2     = (const float*)d_in[16];
    const float* ffn_w2b    = (const float*)d_in[17];
    const float* gamma1     = (const float*)d_in[18];
    const float* gamma2     = (const float*)d_in[19];
    const float* gamma3     = (const float*)d_in[20];
    float* out = (float*)d_out;

    __half *xn, *qkv, *att, *h1, *wbuf;
    float *x1, *gram, *Amat;
    cudaGetSymbolAddress((void**)&xn,   g_xn);
    cudaGetSymbolAddress((void**)&qkv,  g_qkv);
    cudaGetSymbolAddress((void**)&att,  g_att);
    cudaGetSymbolAddress((void**)&h1,   g_h1);
    cudaGetSymbolAddress((void**)&x1,   g_x1);
    cudaGetSymbolAddress((void**)&gram, g_gram);
    cudaGetSymbolAddress((void**)&Amat, g_A);
    cudaGetSymbolAddress((void**)&wbuf, g_wbuf);

    const int smemB = GEMM_SMEM;  // 71680
    cudaFuncSetAttribute(gemm_f16_kernel<0>, cudaFuncAttributeMaxDynamicSharedMemorySize, smemB);
    cudaFuncSetAttribute(gemm_f16_kernel<1>, cudaFuncAttributeMaxDynamicSharedMemorySize, smemB);
    cudaFuncSetAttribute(gemm_f16_kernel<2>, cudaFuncAttributeMaxDynamicSharedMemorySize, smemB);
    cudaFuncSetAttribute(gemm_f16_kernel<3>, cudaFuncAttributeMaxDynamicSharedMemorySize, smemB);
    cudaFuncSetAttribute(gemm_f16_kernel<4>, cudaFuncAttributeMaxDynamicSharedMemorySize, smemB);

    f2h_all_kernel<<<(W_TOTAL / 4 + 255) / 256, 256>>>(
        sa_qkv_w, sa_proj_w, ca_qkv_w, ca_proj_w, ffn_w1, ffn_w2, wbuf);

    const int lnBlocks = TOK / 8;

    // ---- stage 1: window attention ----
    ln_bchw_kernel<<<lnBlocks, 256>>>(x, sa_norm_w, sa_norm_b, xn);
    gemm_f16_kernel<0><<<dim3(3 * CH / BN, TOK / BM), 256, smemB>>>(
        xn, wbuf + W_SAQKV, qkv, TOK, 3 * CH, CH, nullptr, nullptr, nullptr);
    win_attn_kernel<<<NWIN * NH, 64>>>(qkv, sa_bias_t, att);
    gemm_f16_kernel<2><<<dim3(CH / BN, TOK / BM), 256, smemB>>>(
        att, wbuf + W_SAPROJ, x1, TOK, CH, CH, sa_proj_b, gamma1, x);

    // ---- stage 2: channel attention ----
    ln_row_kernel<<<lnBlocks, 256>>>(x1, ca_norm_w, ca_norm_b, xn);
    gemm_f16_kernel<0><<<dim3(3 * CH / BN, TOK / BM), 256, smemB>>>(
        xn, wbuf + W_CAQKV, qkv, TOK, 3 * CH, CH, nullptr, nullptr, nullptr);
    zero_gram_kernel<<<(NH * BATCH * HD * HD + 255) / 256, 256>>>(gram);
    ca_gram_kernel<<<dim3(NH * BATCH, 16), 576>>>(qkv, gram);
    ca_softmax_kernel<<<NH * BATCH, 32>>>(gram, Amat);
    ca_out_kernel<<<dim3(BATCH, HW / 32), 256>>>(qkv, Amat, att);
    gemm_f16_kernel<3><<<dim3(CH / BN, TOK / BM), 256, smemB>>>(
        att, wbuf + W_CAPROJ, x1, TOK, CH, CH, ca_proj_b, gamma2, x1);

    // ---- stage 3: gated FFN ----
    ln_row_kernel<<<lnBlocks, 256>>>(x1, ffn_norm_w, ffn_norm_b, xn);
    gemm_f16_kernel<1><<<dim3(FFN / BN, TOK / BM), 256, smemB>>>(
        xn, wbuf + W_FFN1, h1, TOK, FFN, CH, ffn_b1, nullptr, nullptr);
    gemm_f16_kernel<4><<<dim3(CH / BN, TOK / BM), 256, smemB>>>(
        h1, wbuf + W_FFN2, out, TOK, CH, FFN, ffn_w2b, gamma3, x1);
}

// round 13
// speedup vs baseline: 1.2967x; 1.0277x over previous
#include <cuda_runtime.h>
#include <cuda_fp16.h>
#include <math.h>
#include <stdint.h>

// ---------------------------------------------------------------------------
// Problem constants
// ---------------------------------------------------------------------------
#define BATCH 8
#define CH    192
#define HH    128
#define WW    128
#define HW    (HH*WW)            // 16384
#define TOK   (BATCH*HW)         // 131072
#define NH    8
#define HD    24
#define WS    8
#define FFN   768
#define NWIN  (BATCH*16*16)      // 2048 windows

// ---------------------------------------------------------------------------
// Scratch (device globals; no runtime allocation allowed)
// ---------------------------------------------------------------------------
__device__ __half g_xn [TOK*CH];
__device__ __half g_qkv[TOK*3*CH];
__device__ __half g_att[TOK*CH];
__device__ __half g_h1 [TOK*FFN];
__device__ float  g_x1 [TOK*CH];
__device__ float  g_gram[NH*BATCH*HD*HD];
__device__ float  g_A   [NH*BATCH*HD*HD];
// packed fp16 weights
#define W_SAQKV 0
#define W_SAPROJ (W_SAQKV + 3*CH*CH)
#define W_CAQKV (W_SAPROJ + CH*CH)
#define W_CAPROJ (W_CAQKV + 3*CH*CH)
#define W_FFN1  (W_CAPROJ + CH*CH)
#define W_FFN2  (W_FFN1 + FFN*CH)
#define W_TOTAL (W_FFN2 + CH*FFN)          // 589824
__device__ __half g_wbuf[W_TOTAL];

__device__ __forceinline__ uint32_t smem_u32(const void* p) {
    return (uint32_t)__cvta_generic_to_shared(p);
}

// ---------------------------------------------------------------------------
// Single merged fp32->fp16 conversion over all 6 weight segments
// ---------------------------------------------------------------------------
__global__ void f2h_all_kernel(const float* __restrict__ w0, const float* __restrict__ w1,
                               const float* __restrict__ w2, const float* __restrict__ w3,
                               const float* __restrict__ w4, const float* __restrict__ w5,
                               __half* __restrict__ out) {
    int i = blockIdx.x * blockDim.x + threadIdx.x;
    int e = i * 4;
    if (e >= W_TOTAL) return;
    const float* src;
    int off;
    if      (e < W_SAPROJ) { src = w0; off = e - W_SAQKV; }
    else if (e < W_CAQKV)  { src = w1; off = e - W_SAPROJ; }
    else if (e < W_CAPROJ) { src = w2; off = e - W_CAQKV; }
    else if (e < W_FFN1)   { src = w3; off = e - W_CAPROJ; }
    else if (e < W_FFN2)   { src = w4; off = e - W_FFN1; }
    else                   { src = w5; off = e - W_FFN2; }
    float4 v = *(const float4*)(src + off);
    *(__half2*)(out + e)     = __floats2half2_rn(v.x, v.y);
    *(__half2*)(out + e + 2) = __floats2half2_rn(v.z, v.w);
}

// ---------------------------------------------------------------------------
// LayerNorms: fp32 in -> fp16 out
// ---------------------------------------------------------------------------
__global__ void ln_bchw_kernel(const float* __restrict__ x,
                               const float* __restrict__ w,
                               const float* __restrict__ bb,
                               __half* __restrict__ out) {
    int gwarp = (blockIdx.x * blockDim.x + threadIdx.x) >> 5;
    int lane  = threadIdx.x & 31;
    if (gwarp >= TOK) return;
    int b = gwarp >> 14;
    int l = gwarp & (HW - 1);
    const float* xp = x + ((size_t)b * CH << 14) + l;
    float v[6];
    float s = 0.f;
#pragma unroll
    for (int j = 0; j < 6; j++) {
        int c = lane + 32 * j;
        v[j] = xp[(size_t)c << 14];
        s += v[j];
    }
#pragma unroll
    for (int o = 16; o > 0; o >>= 1) s += __shfl_xor_sync(0xffffffffu, s, o);
    float mean = s * (1.f / CH);
    float s2 = 0.f;
#pragma unroll
    for (int j = 0; j < 6; j++) { float d = v[j] - mean; s2 += d * d; }
#pragma unroll
    for (int o = 16; o > 0; o >>= 1) s2 += __shfl_xor_sync(0xffffffffu, s2, o);
    float rstd = rsqrtf(s2 * (1.f / CH) + 1e-5f);
    __half* op = out + (size_t)gwarp * CH;
#pragma unroll
    for (int j = 0; j < 6; j++) {
        int c = lane + 32 * j;
        op[c] = __float2half((v[j] - mean) * rstd * w[c] + bb[c]);
    }
}

__global__ void ln_row_kernel(const float* __restrict__ x,
                              const float* __restrict__ w,
                              const float* __restrict__ bb,
                              __half* __restrict__ out) {
    int gwarp = (blockIdx.x * blockDim.x + threadIdx.x) >> 5;
    int lane  = threadIdx.x & 31;
    if (gwarp >= TOK) return;
    const float* xp = x + (size_t)gwarp * CH;
    float v[6];
    float s = 0.f;
#pragma unroll
    for (int j = 0; j < 6; j++) { v[j] = xp[lane + 32 * j]; s += v[j]; }
#pragma unroll
    for (int o = 16; o > 0; o >>= 1) s += __shfl_xor_sync(0xffffffffu, s, o);
    float mean = s * (1.f / CH);
    float s2 = 0.f;
#pragma unroll
    for (int j = 0; j < 6; j++) { float d = v[j] - mean; s2 += d * d; }
#pragma unroll
    for (int o = 16; o > 0; o >>= 1) s2 += __shfl_xor_sync(0xffffffffu, s2, o);
    float rstd = rsqrtf(s2 * (1.f / CH) + 1e-5f);
    __half* op = out + (size_t)gwarp * CH;
#pragma unroll
    for (int j = 0; j < 6; j++) {
        int c = lane + 32 * j;
        op[c] = __float2half((v[j] - mean) * rstd * w[c] + bb[c]);
    }
}

// ---------------------------------------------------------------------------
// FP16 tensor-core GEMM: 128x96x32, 8 warps, 4-stage cp.async, ldmatrix
// fragment loads (5 LDSM per k16 vs 20 LDS.32).
// 80B row stride: matrix rows start at word offsets 20r mod 32 =
// {0,20,8,28,16,4,24,12}, 4 words each -> all 32 banks once: conflict-free.
// ---------------------------------------------------------------------------
#define BM 128
#define BN 96
#define BK 32
#define STAGES 4
#define RSTRIDE 80
#define A_ST_B (BM * RSTRIDE)             // 10240
#define B_ST_B (BN * RSTRIDE)             // 7680
#define ST_B   (A_ST_B + B_ST_B)          // 17920
#define GEMM_SMEM (STAGES * ST_B)         // 71680

__device__ __forceinline__ void cp16(uint32_t dst, const void* src) {
    asm volatile("cp.async.cg.shared.global [%0], [%1], 16;" :: "r"(dst), "l"(src) : "memory");
}
__device__ __forceinline__ void ldsm4(uint32_t& r0, uint32_t& r1, uint32_t& r2, uint32_t& r3,
                                      uint32_t addr) {
    asm volatile("ldmatrix.sync.aligned.m8n8.x4.shared.b16 {%0,%1,%2,%3}, [%4];"
                 : "=r"(r0), "=r"(r1), "=r"(r2), "=r"(r3) : "r"(addr));
}

template<int MODE>
__global__ __launch_bounds__(256, 2)
void gemm_f16_kernel(const __half* __restrict__ A, const __half* __restrict__ W,
                     void* __restrict__ CoutV, int M, int N, int K,
                     const float* __restrict__ bias,
                     const float* __restrict__ gamma,
                     const float* __restrict__ resid) {
    extern __shared__ char sm[];
    const uint32_t smBase = smem_u32(sm);

    const int n0 = blockIdx.x * BN;
    const int m0 = blockIdx.y * BM;
    const int tid  = threadIdx.x;
    const int lane = tid & 31;
    const int wid  = tid >> 5;
    const int wm   = wid & 3;        // 32 rows each
    const int wn   = wid >> 2;       // 48 cols each

    float acc[2][6][4];
#pragma unroll
    for (int i = 0; i < 2; i++)
#pragma unroll
        for (int j = 0; j < 6; j++)
#pragma unroll
            for (int q = 0; q < 4; q++) acc[i][j][q] = 0.f;

    const int nK = K / BK;

    const int ldRow = tid >> 2;
    const int ldC   = tid & 3;

    auto load_stage = [&](int chunk, int st) {
        const int k0 = chunk * BK;
        const uint32_t aB = smBase + st * ST_B;
        const uint32_t bB = aB + A_ST_B;
#pragma unroll
        for (int it = 0; it < 2; it++) {
            int r = ldRow + it * 64;
            cp16(aB + r * RSTRIDE + (ldC << 4), A + (size_t)(m0 + r) * K + k0 + ldC * 8);
        }
        {
            int r = ldRow;
            cp16(bB + r * RSTRIDE + (ldC << 4), W + (size_t)(n0 + r) * K + k0 + ldC * 8);
        }
        if (tid < 128) {
            int r = 64 + ldRow;
            cp16(bB + r * RSTRIDE + (ldC << 4), W + (size_t)(n0 + r) * K + k0 + ldC * 8);
        }
        asm volatile("cp.async.commit_group;" ::: "memory");
    };

    load_stage(0, 0);
    load_stage(1, 1);
    load_stage(2, 2);

    // ---- ldmatrix per-lane address offsets (byte offsets within a stage) ----
    const int seg = lane >> 3;        // 0..3
    const int ro  = lane & 7;         // row within matrix
    // A tiles i=0,1: row = wm*32 + i*16 + (seg&1)*8 + ro, k-half = seg>>1
    uint32_t aOff[2];
#pragma unroll
    for (int i = 0; i < 2; i++)
        aOff[i] = (uint32_t)((wm * 32 + i * 16 + (seg & 1) * 8 + ro) * RSTRIDE
                             + ((seg >> 1) << 4));
    // B tile-pairs jp=0,1,2 (cols 16 each): col = wn*48 + jp*16 + (seg>>1)*8 + ro,
    // k-half = seg&1
    uint32_t bOff[3];
#pragma unroll
    for (int jp = 0; jp < 3; jp++)
        bOff[jp] = (uint32_t)(A_ST_B + (wn * 48 + jp * 16 + (seg >> 1) * 8 + ro) * RSTRIDE
                              + ((seg & 1) << 4));

    for (int kt = 0; kt < nK; kt++) {
        asm volatile("cp.async.wait_group %0;" :: "n"(STAGES - 2) : "memory");
        __syncthreads();

        if (kt + STAGES - 1 < nK) load_stage(kt + STAGES - 1, (kt + STAGES - 1) & (STAGES - 1));
        else asm volatile("cp.async.commit_group;" ::: "memory");

        const uint32_t stB = smBase + (kt & (STAGES - 1)) * ST_B;

#pragma unroll
        for (int g = 0; g < 2; g++) {
            const uint32_t gk = g * 32;
            uint32_t a[2][4];
#pragma unroll
            for (int i = 0; i < 2; i++)
                ldsm4(a[i][0], a[i][1], a[i][2], a[i][3], stB + aOff[i] + gk);
            uint32_t b[6][2];
#pragma unroll
            for (int jp = 0; jp < 3; jp++)
                ldsm4(b[jp*2][0], b[jp*2][1], b[jp*2+1][0], b[jp*2+1][1], stB + bOff[jp] + gk);
#pragma unroll
            for (int i = 0; i < 2; i++)
#pragma unroll
                for (int j = 0; j < 6; j++) {
                    asm volatile(
                        "mma.sync.aligned.m16n8k16.row.col.f32.f16.f16.f32 "
                        "{%0,%1,%2,%3},{%4,%5,%6,%7},{%8,%9},{%0,%1,%2,%3};"
                        : "+f"(acc[i][j][0]), "+f"(acc[i][j][1]),
                          "+f"(acc[i][j][2]), "+f"(acc[i][j][3])
                        : "r"(a[i][0]), "r"(a[i][1]), "r"(a[i][2]), "r"(a[i][3]),
                          "r"(b[j][0]), "r"(b[j][1]));
                }
        }
        __syncthreads();
    }

    // ---- epilogue ----
    const int rq = lane >> 2;
    const int cq = (lane & 3) * 2;
    __half* Ch = (__half*)CoutV;
    float*  Cf = (float*)CoutV;
#pragma unroll
    for (int i = 0; i < 2; i++) {
#pragma unroll
        for (int j = 0; j < 6; j++) {
#pragma unroll
            for (int half_ = 0; half_ < 2; half_++) {
                int m = m0 + wm * 32 + i * 16 + rq + half_ * 8;
                int n = n0 + wn * 48 + j * 8 + cq;
                float v0 = acc[i][j][half_ * 2 + 0];
                float v1 = acc[i][j][half_ * 2 + 1];
                if (MODE == 0) {
                    *(__half2*)(Ch + (size_t)m * N + n) = __floats2half2_rn(v0, v1);
                } else if (MODE == 1) {
                    v0 += bias[n];     v1 += bias[n + 1];
                    v0 = 0.5f * v0 * (1.0f + erff(v0 * 0.70710678118654752f));
                    v1 = 0.5f * v1 * (1.0f + erff(v1 * 0.70710678118654752f));
                    *(__half2*)(Ch + (size_t)m * N + n) = __floats2half2_rn(v0, v1);
                } else if (MODE == 2) {
                    int bb_ = m >> 14, l = m & (HW - 1);
                    float r0 = resid[((size_t)(bb_ * CH + n)     << 14) + l];
                    float r1 = resid[((size_t)(bb_ * CH + n + 1) << 14) + l];
                    float2 o;
                    o.x = r0 + gamma[n]     * (v0 + bias[n]);
                    o.y = r1 + gamma[n + 1] * (v1 + bias[n + 1]);
                    *(float2*)(Cf + (size_t)m * N + n) = o;
                } else if (MODE == 3) {
                    float2 rr = *(const float2*)(resid + (size_t)m * N + n);
                    float2 o;
                    o.x = rr.x + gamma[n]     * (v0 + bias[n]);
                    o.y = rr.y + gamma[n + 1] * (v1 + bias[n + 1]);
                    *(float2*)(Cf + (size_t)m * N + n) = o;
                } else { // MODE 4
                    int bb_ = m >> 14, l = m & (HW - 1);
                    float r0 = resid[(size_t)m * N + n];
                    float r1 = resid[(size_t)m * N + n + 1];
                    Cf[((size_t)(bb_ * CH + n)     << 14) + l] = r0 + gamma[n]     * (v0 + bias[n]);
                    Cf[((size_t)(bb_ * CH + n + 1) << 14) + l] = r1 + gamma[n + 1] * (v1 + bias[n + 1]);
                }
            }
        }
    }
}

// ---------------------------------------------------------------------------
// Window attention: online softmax, float4 smem reads, uint4 global loads
// ---------------------------------------------------------------------------
__global__ __launch_bounds__(64)
void win_attn_kernel(const __half* __restrict__ qkv,
                     const float* __restrict__ table,
                     __half* __restrict__ out) {
    int h   = blockIdx.x & 7;
    int wid = blockIdx.x >> 3;
    int b   = wid >> 8;
    int rem = wid & 255;
    int wy  = rem >> 4, wx = rem & 15;

    int i  = threadIdx.x;
    int iy = i >> 3, ix = i & 7;
    int t  = (b << 14) + ((wy * 8 + iy) << 7) + wx * 8 + ix;

    __shared__ float ks[64][24];
    __shared__ float vs[64][24];
    __shared__ float bt[240];
    for (int p = i; p < 225; p += 64) bt[p] = table[p * NH + h];

    const uint4* rowp = (const uint4*)(qkv + (size_t)t * (3 * CH) + h * HD);
    float q[24];
#pragma unroll
    for (int c4 = 0; c4 < 3; c4++) {
        uint4 qv = rowp[c4];
        uint4 kv = rowp[c4 + CH / 8];
        uint4 vv = rowp[c4 + 2 * CH / 8];
        const __half2* qh = (const __half2*)&qv;
        const __half2* kh = (const __half2*)&kv;
        const __half2* vh = (const __half2*)&vv;
#pragma unroll
        for (int p = 0; p < 4; p++) {
            float2 qf = __half22float2(qh[p]);
            float2 kf = __half22float2(kh[p]);
            float2 vf = __half22float2(vh[p]);
            q[c4 * 8 + p * 2]     = qf.x;
            q[c4 * 8 + p * 2 + 1] = qf.y;
            ks[i][c4 * 8 + p * 2]     = kf.x;
            ks[i][c4 * 8 + p * 2 + 1] = kf.y;
            vs[i][c4 * 8 + p * 2]     = vf.x;
            vs[i][c4 * 8 + p * 2 + 1] = vf.y;
        }
    }
    __syncthreads();

    const float scale = 0.20412414523193154f;
    float mx = -1e30f;
    float sum = 0.f;
    float accum[24];
#pragma unroll
    for (int d = 0; d < HD; d++) accum[d] = 0.f;

#pragma unroll 2
    for (int j = 0; j < 64; j++) {
        int jy = j >> 3, jx = j & 7;
        const float4* kr = (const float4*)&ks[j][0];
        float4 k0 = kr[0], k1 = kr[1], k2 = kr[2], k3 = kr[3], k4 = kr[4], k5 = kr[5];
        float dot =
            q[0]*k0.x + q[1]*k0.y + q[2]*k0.z + q[3]*k0.w +
            q[4]*k1.x + q[5]*k1.y + q[6]*k1.z + q[7]*k1.w +
            q[8]*k2.x + q[9]*k2.y + q[10]*k2.z + q[11]*k2.w +
            q[12]*k3.x + q[13]*k3.y + q[14]*k3.z + q[15]*k3.w +
            q[16]*k4.x + q[17]*k4.y + q[18]*k4.z + q[19]*k4.w +
            q[20]*k5.x + q[21]*k5.y + q[22]*k5.z + q[23]*k5.w;
        dot = dot * scale + bt[(iy - jy + 7) * 15 + (ix - jx + 7)];

        if (dot > mx) {
            float rs = __expf(mx - dot);
            sum *= rs;
#pragma unroll
            for (int d = 0; d < HD; d++) accum[d] *= rs;
            mx = dot;
        }
        float p = __expf(dot - mx);
        sum += p;
        const float4* vr = (const float4*)&vs[j][0];
        float4 v0 = vr[0], v1 = vr[1], v2 = vr[2], v3 = vr[3], v4 = vr[4], v5 = vr[5];
        accum[0]  += p * v0.x;  accum[1]  += p * v0.y;  accum[2]  += p * v0.z;  accum[3]  += p * v0.w;
        accum[4]  += p * v1.x;  accum[5]  += p * v1.y;  accum[6]  += p * v1.z;  accum[7]  += p * v1.w;
        accum[8]  += p * v2.x;  accum[9]  += p * v2.y;  accum[10] += p * v2.z;  accum[11] += p * v2.w;
        accum[12] += p * v3.x;  accum[13] += p * v3.y;  accum[14] += p * v3.z;  accum[15] += p * v3.w;
        accum[16] += p * v4.x;  accum[17] += p * v4.y;  accum[18] += p * v4.z;  accum[19] += p * v4.w;
        accum[20] += p * v5.x;  accum[21] += p * v5.y;  accum[22] += p * v5.z;  accum[23] += p * v5.w;
    }
    float inv = 1.f / sum;

    __half* op = out + (size_t)t * CH + h * HD;
    uint4 ov[3];
    __half2* oh = (__half2*)ov;
#pragma unroll
    for (int p = 0; p < 12; p++)
        oh[p] = __floats2half2_rn(accum[p * 2] * inv, accum[p * 2 + 1] * inv);
    uint4* op4 = (uint4*)op;
#pragma unroll
    for (int c4 = 0; c4 < 3; c4++) op4[c4] = ov[c4];
}

// ---------------------------------------------------------------------------
// Channel attention
// ---------------------------------------------------------------------------
__global__ __launch_bounds__(576)
void ca_gram_kernel(const __half* __restrict__ qkv, float* __restrict__ gram) {
    int bh = blockIdx.x;
    int b = bh >> 3, h = bh & 7;
    int tid = threadIdx.x;
    int d = tid / 24, e = tid - d * 24;

    __shared__ float qs[64][24];
    __shared__ float ks[64][24];

    const int chunk = HW / 16;
    int l0 = blockIdx.y * chunk;
    float accum = 0.f;
    for (int tile = 0; tile < chunk; tile += 64) {
        for (int p = tid; p < 64 * 24; p += 576) {
            int tok = p / 24, dd = p - tok * 24;
            size_t base = (size_t)((b << 14) + l0 + tile + tok) * (3 * CH) + h * HD + dd;
            qs[tok][dd] = __half2float(qkv[base]);
            ks[tok][dd] = __half2float(qkv[base + CH]);
        }
        __syncthreads();
#pragma unroll 8
        for (int tok = 0; tok < 64; tok++) accum += qs[tok][d] * ks[tok][e];
        __syncthreads();
    }
    atomicAdd(&gram[bh * (HD * HD) + tid], accum);
}

__global__ void zero_gram_kernel(float* __restrict__ gram) {
    int i = blockIdx.x * blockDim.x + threadIdx.x;
    if (i < NH * BATCH * HD * HD) gram[i] = 0.f;
}

__global__ void ca_softmax_kernel(const float* __restrict__ gram, float* __restrict__ A) {
    int bh = blockIdx.x;
    int d = threadIdx.x;
    if (d >= HD) return;
    const float scale = 0.20412414523193154f;
    float r[24];
    float mx = -1e30f;
#pragma unroll
    for (int e = 0; e < HD; e++) {
        r[e] = gram[bh * (HD * HD) + d * HD + e] * scale;
        mx = fmaxf(mx, r[e]);
    }
    float sum = 0.f;
#pragma unroll
    for (int e = 0; e < HD; e++) { r[e] = __expf(r[e] - mx); sum += r[e]; }
    float inv = 1.f / sum;
#pragma unroll
    for (int e = 0; e < HD; e++) A[bh * (HD * HD) + d * HD + e] = r[e] * inv;
}

__global__ __launch_bounds__(256)
void ca_out_kernel(const __half* __restrict__ qkv, const float* __restrict__ A,
                   __half* __restrict__ out) {
    int b  = blockIdx.x;
    int l0 = blockIdx.y * 32;
    int tid = threadIdx.x;
    __shared__ float vs[32][192];
    for (int p = tid; p < 32 * 192; p += 256) {
        int tok = p / 192, c = p - tok * 192;
        vs[tok][c] = __half2float(qkv[(size_t)((b << 14) + l0 + tok) * (3 * CH) + 2 * CH + c]);
    }
    __syncthreads();
    int tok = tid >> 3;
    int h   = tid & 7;
    int t   = (b << 14) + l0 + tok;
    const float* Ah = A + (b * 8 + h) * (HD * HD);
    __half* op = out + (size_t)t * CH + h * HD;
#pragma unroll
    for (int d = 0; d < HD; d++) {
        float s = 0.f;
#pragma unroll
        for (int e = 0; e < HD; e++) s += Ah[d * HD + e] * vs[tok][h * HD + e];
        op[d] = __float2half(s);
    }
}

// ---------------------------------------------------------------------------
// Launch
// ---------------------------------------------------------------------------
extern "C" void kernel_launch(void* const* d_in, const int* in_sizes, int n_in,
                              void* d_out, int out_size) {
    const float* x          = (const float*)d_in[0];
    const float* sa_norm_w  = (const float*)d_in[1];
    const float* sa_norm_b  = (const float*)d_in[2];
    const float* sa_qkv_w   = (const float*)d_in[3];
    const float* sa_proj_w  = (const float*)d_in[4];
    const float* sa_proj_b  = (const float*)d_in[5];
    const float* sa_bias_t  = (const float*)d_in[6];
    const float* ca_norm_w  = (const float*)d_in[7];
    const float* ca_norm_b  = (const float*)d_in[8];
    const float* ca_qkv_w   = (const float*)d_in[9];
    const float* ca_proj_w  = (const float*)d_in[10];
    const float* ca_proj_b  = (const float*)d_in[11];
    const float* ffn_norm_w = (const float*)d_in[12];
    const float* ffn_norm_b = (const float*)d_in[13];
    const float* ffn_w1     = (const float*)d_in[14];
    const float* ffn_b1     = (const float*)d_in[15];
    const float* ffn_w2     = (const float*)d_in[16];
    const float* ffn_w2b    = (const float*)d_in[17];
    const float* gamma1     = (const float*)d_in[18];
    const float* gamma2     = (const float*)d_in[19];
    const float* gamma3     = (const float*)d_in[20];
    float* out = (float*)d_out;

    __half *xn, *qkv, *att, *h1, *wbuf;
    float *x1, *gram, *Amat;
    cudaGetSymbolAddress((void**)&xn,   g_xn);
    cudaGetSymbolAddress((void**)&qkv,  g_qkv);
    cudaGetSymbolAddress((void**)&att,  g_att);
    cudaGetSymbolAddress((void**)&h1,   g_h1);
    cudaGetSymbolAddress((void**)&x1,   g_x1);
    cudaGetSymbolAddress((void**)&gram, g_gram);
    cudaGetSymbolAddress((void**)&Amat, g_A);
    cudaGetSymbolAddress((void**)&wbuf, g_wbuf);

    const int smemB = GEMM_SMEM;  // 71680
    cudaFuncSetAttribute(gemm_f16_kernel<0>, cudaFuncAttributeMaxDynamicSharedMemorySize, smemB);
    cudaFuncSetAttribute(gemm_f16_kernel<1>, cudaFuncAttributeMaxDynamicSharedMemorySize, smemB);
    cudaFuncSetAttribute(gemm_f16_kernel<2>, cudaFuncAttributeMaxDynamicSharedMemorySize, smemB);
    cudaFuncSetAttribute(gemm_f16_kernel<3>, cudaFuncAttributeMaxDynamicSharedMemorySize, smemB);
    cudaFuncSetAttribute(gemm_f16_kernel<4>, cudaFuncAttributeMaxDynamicSharedMemorySize, smemB);

    f2h_all_kernel<<<(W_TOTAL / 4 + 255) / 256, 256>>>(
        sa_qkv_w, sa_proj_w, ca_qkv_w, ca_proj_w, ffn_w1, ffn_w2, wbuf);

    const int lnBlocks = TOK / 8;

    // ---- stage 1: window attention ----
    ln_bchw_kernel<<<lnBlocks, 256>>>(x, sa_norm_w, sa_norm_b, xn);
    gemm_f16_kernel<0><<<dim3(3 * CH / BN, TOK / BM), 256, smemB>>>(
        xn, wbuf + W_SAQKV, qkv, TOK, 3 * CH, CH, nullptr, nullptr, nullptr);
    win_attn_kernel<<<NWIN * NH, 64>>>(qkv, sa_bias_t, att);
    gemm_f16_kernel<2><<<dim3(CH / BN, TOK / BM), 256, smemB>>>(
        att, wbuf + W_SAPROJ, x1, TOK, CH, CH, sa_proj_b, gamma1, x);

    // ---- stage 2: channel attention ----
    ln_row_kernel<<<lnBlocks, 256>>>(x1, ca_norm_w, ca_norm_b, xn);
    gemm_f16_kernel<0><<<dim3(3 * CH / BN, TOK / BM), 256, smemB>>>(
        xn, wbuf + W_CAQKV, qkv, TOK, 3 * CH, CH, nullptr, nullptr, nullptr);
    zero_gram_kernel<<<(NH * BATCH * HD * HD + 255) / 256, 256>>>(gram);
    ca_gram_kernel<<<dim3(NH * BATCH, 16), 576>>>(qkv, gram);
    ca_softmax_kernel<<<NH * BATCH, 32>>>(gram, Amat);
    ca_out_kernel<<<dim3(BATCH, HW / 32), 256>>>(qkv, Amat, att);
    gemm_f16_kernel<3><<<dim3(CH / BN, TOK / BM), 256, smemB>>>(
        att, wbuf + W_CAPROJ, x1, TOK, CH, CH, ca_proj_b, gamma2, x1);

    // ---- stage 3: gated FFN ----
    ln_row_kernel<<<lnBlocks, 256>>>(x1, ffn_norm_w, ffn_norm_b, xn);
    gemm_f16_kernel<1><<<dim3(FFN / BN, TOK / BM), 256, smemB>>>(
        xn, wbuf + W_FFN1, h1, TOK, FFN, CH, ffn_b1, nullptr, nullptr);
    gemm_f16_kernel<4><<<dim3(CH / BN, TOK / BM), 256, smemB>>>(
        h1, wbuf + W_FFN2, out, TOK, CH, FFN, ffn_w2b, gamma3, x1);
}

// round 14
// speedup vs baseline: 1.3422x; 1.0351x over previous
#include <cuda_runtime.h>
#include <cuda_fp16.h>
#include <math.h>
#include <stdint.h>

// ---------------------------------------------------------------------------
// Problem constants
// ---------------------------------------------------------------------------
#define BATCH 8
#define CH    192
#define HH    128
#define WW    128
#define HW    (HH*WW)            // 16384
#define TOK   (BATCH*HW)         // 131072
#define NH    8
#define HD    24
#define WS    8
#define FFN   768
#define NWIN  (BATCH*16*16)      // 2048 windows

// ---------------------------------------------------------------------------
// Scratch (device globals; no runtime allocation allowed)
// ---------------------------------------------------------------------------
__device__ __half g_xn [TOK*CH];
__device__ __half g_qkv[TOK*3*CH];
__device__ __half g_att[TOK*CH];
__device__ __half g_h1 [TOK*FFN];
__device__ float  g_x1 [TOK*CH];
__device__ float  g_gram[NH*BATCH*HD*HD];
__device__ float  g_A   [NH*BATCH*HD*HD];
// packed fp16 weights
#define W_SAQKV 0
#define W_SAPROJ (W_SAQKV + 3*CH*CH)
#define W_CAQKV (W_SAPROJ + CH*CH)
#define W_CAPROJ (W_CAQKV + 3*CH*CH)
#define W_FFN1  (W_CAPROJ + CH*CH)
#define W_FFN2  (W_FFN1 + FFN*CH)
#define W_TOTAL (W_FFN2 + CH*FFN)          // 589824
__device__ __half g_wbuf[W_TOTAL];

__device__ __forceinline__ uint32_t smem_u32(const void* p) {
    return (uint32_t)__cvta_generic_to_shared(p);
}

// ---- Blackwell packed f32x2 helpers ----
__device__ __forceinline__ unsigned long long pk2(float lo, float hi) {
    unsigned long long r;
    asm("mov.b64 %0, {%1,%2};" : "=l"(r) : "f"(lo), "f"(hi));
    return r;
}
__device__ __forceinline__ float2 upk2(unsigned long long v) {
    float2 r;
    asm("mov.b64 {%0,%1}, %2;" : "=f"(r.x), "=f"(r.y) : "l"(v));
    return r;
}
__device__ __forceinline__ unsigned long long fma2(unsigned long long a,
                                                   unsigned long long b,
                                                   unsigned long long c) {
    unsigned long long d;
    asm("fma.rn.f32x2 %0, %1, %2, %3;" : "=l"(d) : "l"(a), "l"(b), "l"(c));
    return d;
}
__device__ __forceinline__ unsigned long long mul2(unsigned long long a,
                                                   unsigned long long b) {
    unsigned long long d;
    asm("mul.rn.f32x2 %0, %1, %2;" : "=l"(d) : "l"(a), "l"(b));
    return d;
}

// ---------------------------------------------------------------------------
// Single merged fp32->fp16 conversion over all 6 weight segments
// ---------------------------------------------------------------------------
__global__ void f2h_all_kernel(const float* __restrict__ w0, const float* __restrict__ w1,
                               const float* __restrict__ w2, const float* __restrict__ w3,
                               const float* __restrict__ w4, const float* __restrict__ w5,
                               __half* __restrict__ out) {
    int i = blockIdx.x * blockDim.x + threadIdx.x;
    int e = i * 4;
    if (e >= W_TOTAL) return;
    const float* src;
    int off;
    if      (e < W_SAPROJ) { src = w0; off = e - W_SAQKV; }
    else if (e < W_CAQKV)  { src = w1; off = e - W_SAPROJ; }
    else if (e < W_CAPROJ) { src = w2; off = e - W_CAQKV; }
    else if (e < W_FFN1)   { src = w3; off = e - W_CAPROJ; }
    else if (e < W_FFN2)   { src = w4; off = e - W_FFN1; }
    else                   { src = w5; off = e - W_FFN2; }
    float4 v = *(const float4*)(src + off);
    *(__half2*)(out + e)     = __floats2half2_rn(v.x, v.y);
    *(__half2*)(out + e + 2) = __floats2half2_rn(v.z, v.w);
}

// ---------------------------------------------------------------------------
// ln_bchw v2: coalesced via smem transpose.
// Block = (32 tokens, 1 batch); loads 192x32 fp32 tile l-contiguously,
// computes per-token stats with 8-lane groups, writes fp16 c-contiguously.
// ---------------------------------------------------------------------------
#define LNT 32
__global__ __launch_bounds__(256)
void ln_bchw_kernel(const float* __restrict__ x,
                    const float* __restrict__ w,
                    const float* __restrict__ bb,
                    __half* __restrict__ out) {
    __shared__ float sx[CH][LNT + 1];     // 192*33*4 = 25344 B
    __shared__ float smean[LNT], srstd[LNT];
    const int b  = blockIdx.y;
    const int l0 = blockIdx.x * LNT;
    const int tid = threadIdx.x;

    const float* xb = x + ((size_t)b * CH << 14) + l0;
#pragma unroll
    for (int it = 0; it < 6; it++) {
        int idx = tid + it * 256;          // 0..1535
        int c = idx >> 3, lq = idx & 7;
        float4 v = *(const float4*)(xb + ((size_t)c << 14) + lq * 4);
        sx[c][lq * 4 + 0] = v.x;
        sx[c][lq * 4 + 1] = v.y;
        sx[c][lq * 4 + 2] = v.z;
        sx[c][lq * 4 + 3] = v.w;
    }
    __syncthreads();

    {
        int wid = tid >> 5, lane = tid & 31;
        int tok  = wid * 4 + (lane >> 3);
        int part = lane & 7;
        float s = 0.f, s2 = 0.f;
#pragma unroll
        for (int j = 0; j < 24; j++) {
            float v = sx[part + 8 * j][tok];
            s += v; s2 += v * v;
        }
#pragma unroll
        for (int o = 4; o > 0; o >>= 1) {
            s  += __shfl_xor_sync(0xffffffffu, s,  o);
            s2 += __shfl_xor_sync(0xffffffffu, s2, o);
        }
        if (part == 0) {
            float mean = s * (1.f / CH);
            float var  = s2 * (1.f / CH) - mean * mean;
            smean[tok] = mean;
            srstd[tok] = rsqrtf(var + 1e-5f);
        }
    }
    __syncthreads();

#pragma unroll
    for (int it = 0; it < 12; it++) {
        int idx = tid + it * 256;          // 0..3071
        int tok = idx / 96, cp = idx - tok * 96;
        int c = cp * 2;
        float mean = smean[tok], rstd = srstd[tok];
        float v0 = (sx[c][tok]     - mean) * rstd * w[c]     + bb[c];
        float v1 = (sx[c + 1][tok] - mean) * rstd * w[c + 1] + bb[c + 1];
        *(__half2*)(out + (size_t)((b << 14) + l0 + tok) * CH + c) =
            __floats2half2_rn(v0, v1);
    }
}

// ---------------------------------------------------------------------------
// ln_row: fp32 row-major in -> fp16 out (coalesced; one warp per token)
// ---------------------------------------------------------------------------
__global__ void ln_row_kernel(const float* __restrict__ x,
                              const float* __restrict__ w,
                              const float* __restrict__ bb,
                              __half* __restrict__ out) {
    int gwarp = (blockIdx.x * blockDim.x + threadIdx.x) >> 5;
    int lane  = threadIdx.x & 31;
    if (gwarp >= TOK) return;
    const float* xp = x + (size_t)gwarp * CH;
    float v[6];
    float s = 0.f;
#pragma unroll
    for (int j = 0; j < 6; j++) { v[j] = xp[lane + 32 * j]; s += v[j]; }
#pragma unroll
    for (int o = 16; o > 0; o >>= 1) s += __shfl_xor_sync(0xffffffffu, s, o);
    float mean = s * (1.f / CH);
    float s2 = 0.f;
#pragma unroll
    for (int j = 0; j < 6; j++) { float d = v[j] - mean; s2 += d * d; }
#pragma unroll
    for (int o = 16; o > 0; o >>= 1) s2 += __shfl_xor_sync(0xffffffffu, s2, o);
    float rstd = rsqrtf(s2 * (1.f / CH) + 1e-5f);
    __half* op = out + (size_t)gwarp * CH;
#pragma unroll
    for (int j = 0; j < 6; j++) {
        int c = lane + 32 * j;
        op[c] = __float2half((v[j] - mean) * rstd * w[c] + bb[c]);
    }
}

// ---------------------------------------------------------------------------
// FP16 tensor-core GEMM: 128x96x32, 8 warps, 4-stage cp.async, ldmatrix
// ---------------------------------------------------------------------------
#define BM 128
#define BN 96
#define BK 32
#define STAGES 4
#define RSTRIDE 80
#define A_ST_B (BM * RSTRIDE)             // 10240
#define B_ST_B (BN * RSTRIDE)             // 7680
#define ST_B   (A_ST_B + B_ST_B)          // 17920
#define GEMM_SMEM (STAGES * ST_B)         // 71680

__device__ __forceinline__ void cp16(uint32_t dst, const void* src) {
    asm volatile("cp.async.cg.shared.global [%0], [%1], 16;" :: "r"(dst), "l"(src) : "memory");
}
__device__ __forceinline__ void ldsm4(uint32_t& r0, uint32_t& r1, uint32_t& r2, uint32_t& r3,
                                      uint32_t addr) {
    asm volatile("ldmatrix.sync.aligned.m8n8.x4.shared.b16 {%0,%1,%2,%3}, [%4];"
                 : "=r"(r0), "=r"(r1), "=r"(r2), "=r"(r3) : "r"(addr));
}

template<int MODE>
__global__ __launch_bounds__(256, 2)
void gemm_f16_kernel(const __half* __restrict__ A, const __half* __restrict__ W,
                     void* __restrict__ CoutV, int M, int N, int K,
                     const float* __restrict__ bias,
                     const float* __restrict__ gamma,
                     const float* __restrict__ resid) {
    extern __shared__ char sm[];
    const uint32_t smBase = smem_u32(sm);

    const int n0 = blockIdx.x * BN;
    const int m0 = blockIdx.y * BM;
    const int tid  = threadIdx.x;
    const int lane = tid & 31;
    const int wid  = tid >> 5;
    const int wm   = wid & 3;
    const int wn   = wid >> 2;

    float acc[2][6][4];
#pragma unroll
    for (int i = 0; i < 2; i++)
#pragma unroll
        for (int j = 0; j < 6; j++)
#pragma unroll
            for (int q = 0; q < 4; q++) acc[i][j][q] = 0.f;

    const int nK = K / BK;

    const int ldRow = tid >> 2;
    const int ldC   = tid & 3;

    auto load_stage = [&](int chunk, int st) {
        const int k0 = chunk * BK;
        const uint32_t aB = smBase + st * ST_B;
        const uint32_t bB = aB + A_ST_B;
#pragma unroll
        for (int it = 0; it < 2; it++) {
            int r = ldRow + it * 64;
            cp16(aB + r * RSTRIDE + (ldC << 4), A + (size_t)(m0 + r) * K + k0 + ldC * 8);
        }
        {
            int r = ldRow;
            cp16(bB + r * RSTRIDE + (ldC << 4), W + (size_t)(n0 + r) * K + k0 + ldC * 8);
        }
        if (tid < 128) {
            int r = 64 + ldRow;
            cp16(bB + r * RSTRIDE + (ldC << 4), W + (size_t)(n0 + r) * K + k0 + ldC * 8);
        }
        asm volatile("cp.async.commit_group;" ::: "memory");
    };

    load_stage(0, 0);
    load_stage(1, 1);
    load_stage(2, 2);

    const int seg = lane >> 3;
    const int ro  = lane & 7;
    uint32_t aOff[2];
#pragma unroll
    for (int i = 0; i < 2; i++)
        aOff[i] = (uint32_t)((wm * 32 + i * 16 + (seg & 1) * 8 + ro) * RSTRIDE
                             + ((seg >> 1) << 4));
    uint32_t bOff[3];
#pragma unroll
    for (int jp = 0; jp < 3; jp++)
        bOff[jp] = (uint32_t)(A_ST_B + (wn * 48 + jp * 16 + (seg >> 1) * 8 + ro) * RSTRIDE
                              + ((seg & 1) << 4));

    for (int kt = 0; kt < nK; kt++) {
        asm volatile("cp.async.wait_group %0;" :: "n"(STAGES - 2) : "memory");
        __syncthreads();

        if (kt + STAGES - 1 < nK) load_stage(kt + STAGES - 1, (kt + STAGES - 1) & (STAGES - 1));
        else asm volatile("cp.async.commit_group;" ::: "memory");

        const uint32_t stB = smBase + (kt & (STAGES - 1)) * ST_B;

#pragma unroll
        for (int g = 0; g < 2; g++) {
            const uint32_t gk = g * 32;
            uint32_t a[2][4];
#pragma unroll
            for (int i = 0; i < 2; i++)
                ldsm4(a[i][0], a[i][1], a[i][2], a[i][3], stB + aOff[i] + gk);
            uint32_t b[6][2];
#pragma unroll
            for (int jp = 0; jp < 3; jp++)
                ldsm4(b[jp*2][0], b[jp*2][1], b[jp*2+1][0], b[jp*2+1][1], stB + bOff[jp] + gk);
#pragma unroll
            for (int i = 0; i < 2; i++)
#pragma unroll
                for (int j = 0; j < 6; j++) {
                    asm volatile(
                        "mma.sync.aligned.m16n8k16.row.col.f32.f16.f16.f32 "
                        "{%0,%1,%2,%3},{%4,%5,%6,%7},{%8,%9},{%0,%1,%2,%3};"
                        : "+f"(acc[i][j][0]), "+f"(acc[i][j][1]),
                          "+f"(acc[i][j][2]), "+f"(acc[i][j][3])
                        : "r"(a[i][0]), "r"(a[i][1]), "r"(a[i][2]), "r"(a[i][3]),
                          "r"(b[j][0]), "r"(b[j][1]));
                }
        }
        __syncthreads();
    }

    const int rq = lane >> 2;
    const int cq = (lane & 3) * 2;
    __half* Ch = (__half*)CoutV;
    float*  Cf = (float*)CoutV;
#pragma unroll
    for (int i = 0; i < 2; i++) {
#pragma unroll
        for (int j = 0; j < 6; j++) {
#pragma unroll
            for (int half_ = 0; half_ < 2; half_++) {
                int m = m0 + wm * 32 + i * 16 + rq + half_ * 8;
                int n = n0 + wn * 48 + j * 8 + cq;
                float v0 = acc[i][j][half_ * 2 + 0];
                float v1 = acc[i][j][half_ * 2 + 1];
                if (MODE == 0) {
                    *(__half2*)(Ch + (size_t)m * N + n) = __floats2half2_rn(v0, v1);
                } else if (MODE == 1) {
                    v0 += bias[n];     v1 += bias[n + 1];
                    v0 = 0.5f * v0 * (1.0f + erff(v0 * 0.70710678118654752f));
                    v1 = 0.5f * v1 * (1.0f + erff(v1 * 0.70710678118654752f));
                    *(__half2*)(Ch + (size_t)m * N + n) = __floats2half2_rn(v0, v1);
                } else if (MODE == 2) {
                    int bb_ = m >> 14, l = m & (HW - 1);
                    float r0 = resid[((size_t)(bb_ * CH + n)     << 14) + l];
                    float r1 = resid[((size_t)(bb_ * CH + n + 1) << 14) + l];
                    float2 o;
                    o.x = r0 + gamma[n]     * (v0 + bias[n]);
                    o.y = r1 + gamma[n + 1] * (v1 + bias[n + 1]);
                    *(float2*)(Cf + (size_t)m * N + n) = o;
                } else if (MODE == 3) {
                    float2 rr = *(const float2*)(resid + (size_t)m * N + n);
                    float2 o;
                    o.x = rr.x + gamma[n]     * (v0 + bias[n]);
                    o.y = rr.y + gamma[n + 1] * (v1 + bias[n + 1]);
                    *(float2*)(Cf + (size_t)m * N + n) = o;
                } else { // MODE 4
                    int bb_ = m >> 14, l = m & (HW - 1);
                    float r0 = resid[(size_t)m * N + n];
                    float r1 = resid[(size_t)m * N + n + 1];
                    Cf[((size_t)(bb_ * CH + n)     << 14) + l] = r0 + gamma[n]     * (v0 + bias[n]);
                    Cf[((size_t)(bb_ * CH + n + 1) << 14) + l] = r1 + gamma[n + 1] * (v1 + bias[n + 1]);
                }
            }
        }
    }
}

// ---------------------------------------------------------------------------
// Window attention v3: online softmax + packed f32x2 FMA (Blackwell).
// k/v smem rows read as double (LDS.64 -> packed f32x2 operand, free cast).
// ---------------------------------------------------------------------------
__global__ __launch_bounds__(64)
void win_attn_kernel(const __half* __restrict__ qkv,
                     const float* __restrict__ table,
                     __half* __restrict__ out) {
    int h   = blockIdx.x & 7;
    int wid = blockIdx.x >> 3;
    int b   = wid >> 8;
    int rem = wid & 255;
    int wy  = rem >> 4, wx = rem & 15;

    int i  = threadIdx.x;
    int iy = i >> 3, ix = i & 7;
    int t  = (b << 14) + ((wy * 8 + iy) << 7) + wx * 8 + ix;

    __shared__ float ks[64][24];   // row = 96B, 16B aligned
    __shared__ float vs[64][24];
    __shared__ float bt[240];
    for (int p = i; p < 225; p += 64) bt[p] = table[p * NH + h];

    const uint4* rowp = (const uint4*)(qkv + (size_t)t * (3 * CH) + h * HD);
    unsigned long long qp[12];
#pragma unroll
    for (int c4 = 0; c4 < 3; c4++) {
        uint4 qv = rowp[c4];
        uint4 kv = rowp[c4 + CH / 8];
        uint4 vv = rowp[c4 + 2 * CH / 8];
        const __half2* qh = (const __half2*)&qv;
        const __half2* kh = (const __half2*)&kv;
        const __half2* vh = (const __half2*)&vv;
#pragma unroll
        for (int p = 0; p < 4; p++) {
            float2 qf = __half22float2(qh[p]);
            float2 kf = __half22float2(kh[p]);
            float2 vf = __half22float2(vh[p]);
            qp[c4 * 4 + p] = pk2(qf.x, qf.y);
            ks[i][c4 * 8 + p * 2]     = kf.x;
            ks[i][c4 * 8 + p * 2 + 1] = kf.y;
            vs[i][c4 * 8 + p * 2]     = vf.x;
            vs[i][c4 * 8 + p * 2 + 1] = vf.y;
        }
    }
    __syncthreads();

    const float scale = 0.20412414523193154f;
    float mx = -1e30f;
    float sum = 0.f;
    unsigned long long ap[12];
#pragma unroll
    for (int d = 0; d < 12; d++) ap[d] = 0ull;

#pragma unroll 2
    for (int j = 0; j < 64; j++) {
        int jy = j >> 3, jx = j & 7;
        const double* kr = (const double*)&ks[j][0];
        unsigned long long dp = 0ull;
#pragma unroll
        for (int d = 0; d < 12; d++)
            dp = fma2(__double_as_longlong(kr[d]), qp[d], dp);
        float2 dd = upk2(dp);
        float dot = (dd.x + dd.y) * scale + bt[(iy - jy + 7) * 15 + (ix - jx + 7)];

        if (dot > mx) {
            float rs = __expf(mx - dot);
            sum *= rs;
            unsigned long long rp = pk2(rs, rs);
#pragma unroll
            for (int d = 0; d < 12; d++) ap[d] = mul2(ap[d], rp);
            mx = dot;
        }
        float p = __expf(dot - mx);
        sum += p;
        unsigned long long pp = pk2(p, p);
        const double* vr = (const double*)&vs[j][0];
#pragma unroll
        for (int d = 0; d < 12; d++)
            ap[d] = fma2(pp, __double_as_longlong(vr[d]), ap[d]);
    }
    float inv = 1.f / sum;

    __half* op = out + (size_t)t * CH + h * HD;
    uint4 ov[3];
    __half2* oh = (__half2*)ov;
#pragma unroll
    for (int d = 0; d < 12; d++) {
        float2 a = upk2(ap[d]);
        oh[d] = __floats2half2_rn(a.x * inv, a.y * inv);
    }
    uint4* op4 = (uint4*)op;
#pragma unroll
    for (int c4 = 0; c4 < 3; c4++) op4[c4] = ov[c4];
}

// ---------------------------------------------------------------------------
// Channel attention
// ---------------------------------------------------------------------------
__global__ __launch_bounds__(576)
void ca_gram_kernel(const __half* __restrict__ qkv, float* __restrict__ gram) {
    int bh = blockIdx.x;
    int b = bh >> 3, h = bh & 7;
    int tid = threadIdx.x;
    int d = tid / 24, e = tid - d * 24;

    __shared__ float qs[64][24];
    __shared__ float ks[64][24];

    const int chunk = HW / 16;
    int l0 = blockIdx.y * chunk;
    float accum = 0.f;
    for (int tile = 0; tile < chunk; tile += 64) {
        for (int p = tid; p < 64 * 24; p += 576) {
            int tok = p / 24, dd = p - tok * 24;
            size_t base = (size_t)((b << 14) + l0 + tile + tok) * (3 * CH) + h * HD + dd;
            qs[tok][dd] = __half2float(qkv[base]);
            ks[tok][dd] = __half2float(qkv[base + CH]);
        }
        __syncthreads();
#pragma unroll 8
        for (int tok = 0; tok < 64; tok++) accum += qs[tok][d] * ks[tok][e];
        __syncthreads();
    }
    atomicAdd(&gram[bh * (HD * HD) + tid], accum);
}

__global__ void zero_gram_kernel(float* __restrict__ gram) {
    int i = blockIdx.x * blockDim.x + threadIdx.x;
    if (i < NH * BATCH * HD * HD) gram[i] = 0.f;
}

__global__ void ca_softmax_kernel(const float* __restrict__ gram, float* __restrict__ A) {
    int bh = blockIdx.x;
    int d = threadIdx.x;
    if (d >= HD) return;
    const float scale = 0.20412414523193154f;
    float r[24];
    float mx = -1e30f;
#pragma unroll
    for (int e = 0; e < HD; e++) {
        r[e] = gram[bh * (HD * HD) + d * HD + e] * scale;
        mx = fmaxf(mx, r[e]);
    }
    float sum = 0.f;
#pragma unroll
    for (int e = 0; e < HD; e++) { r[e] = __expf(r[e] - mx); sum += r[e]; }
    float inv = 1.f / sum;
#pragma unroll
    for (int e = 0; e < HD; e++) A[bh * (HD * HD) + d * HD + e] = r[e] * inv;
}

__global__ __launch_bounds__(256)
void ca_out_kernel(const __half* __restrict__ qkv, const float* __restrict__ A,
                   __half* __restrict__ out) {
    int b  = blockIdx.x;
    int l0 = blockIdx.y * 32;
    int tid = threadIdx.x;
    __shared__ float vs[32][192];
    for (int p = tid; p < 32 * 192; p += 256) {
        int tok = p / 192, c = p - tok * 192;
        vs[tok][c] = __half2float(qkv[(size_t)((b << 14) + l0 + tok) * (3 * CH) + 2 * CH + c]);
    }
    __syncthreads();
    int tok = tid >> 3;
    int h   = tid & 7;
    int t   = (b << 14) + l0 + tok;
    const float* Ah = A + (b * 8 + h) * (HD * HD);
    __half* op = out + (size_t)t * CH + h * HD;
#pragma unroll
    for (int d = 0; d < HD; d++) {
        float s = 0.f;
#pragma unroll
        for (int e = 0; e < HD; e++) s += Ah[d * HD + e] * vs[tok][h * HD + e];
        op[d] = __float2half(s);
    }
}

// ---------------------------------------------------------------------------
// Launch
// ---------------------------------------------------------------------------
extern "C" void kernel_launch(void* const* d_in, const int* in_sizes, int n_in,
                              void* d_out, int out_size) {
    const float* x          = (const float*)d_in[0];
    const float* sa_norm_w  = (const float*)d_in[1];
    const float* sa_norm_b  = (const float*)d_in[2];
    const float* sa_qkv_w   = (const float*)d_in[3];
    const float* sa_proj_w  = (const float*)d_in[4];
    const float* sa_proj_b  = (const float*)d_in[5];
    const float* sa_bias_t  = (const float*)d_in[6];
    const float* ca_norm_w  = (const float*)d_in[7];
    const float* ca_norm_b  = (const float*)d_in[8];
    const float* ca_qkv_w   = (const float*)d_in[9];
    const float* ca_proj_w  = (const float*)d_in[10];
    const float* ca_proj_b  = (const float*)d_in[11];
    const float* ffn_norm_w = (const float*)d_in[12];
    const float* ffn_norm_b = (const float*)d_in[13];
    const float* ffn_w1     = (const float*)d_in[14];
    const float* ffn_b1     = (const float*)d_in[15];
    const float* ffn_w2     = (const float*)d_in[16];
    const float* ffn_w2b    = (const float*)d_in[17];
    const float* gamma1     = (const float*)d_in[18];
    const float* gamma2     = (const float*)d_in[19];
    const float* gamma3     = (const float*)d_in[20];
    float* out = (float*)d_out;

    __half *xn, *qkv, *att, *h1, *wbuf;
    float *x1, *gram, *Amat;
    cudaGetSymbolAddress((void**)&xn,   g_xn);
    cudaGetSymbolAddress((void**)&qkv,  g_qkv);
    cudaGetSymbolAddress((void**)&att,  g_att);
    cudaGetSymbolAddress((void**)&h1,   g_h1);
    cudaGetSymbolAddress((void**)&x1,   g_x1);
    cudaGetSymbolAddress((void**)&gram, g_gram);
    cudaGetSymbolAddress((void**)&Amat, g_A);
    cudaGetSymbolAddress((void**)&wbuf, g_wbuf);

    const int smemB = GEMM_SMEM;  // 71680
    cudaFuncSetAttribute(gemm_f16_kernel<0>, cudaFuncAttributeMaxDynamicSharedMemorySize, smemB);
    cudaFuncSetAttribute(gemm_f16_kernel<1>, cudaFuncAttributeMaxDynamicSharedMemorySize, smemB);
    cudaFuncSetAttribute(gemm_f16_kernel<2>, cudaFuncAttributeMaxDynamicSharedMemorySize, smemB);
    cudaFuncSetAttribute(gemm_f16_kernel<3>, cudaFuncAttributeMaxDynamicSharedMemorySize, smemB);
    cudaFuncSetAttribute(gemm_f16_kernel<4>, cudaFuncAttributeMaxDynamicSharedMemorySize, smemB);

    f2h_all_kernel<<<(W_TOTAL / 4 + 255) / 256, 256>>>(
        sa_qkv_w, sa_proj_w, ca_qkv_w, ca_proj_w, ffn_w1, ffn_w2, wbuf);

    const int lnBlocks = TOK / 8;

    // ---- stage 1: window attention ----
    ln_bchw_kernel<<<dim3(HW / LNT, BATCH), 256>>>(x, sa_norm_w, sa_norm_b, xn);
    gemm_f16_kernel<0><<<dim3(3 * CH / BN, TOK / BM), 256, smemB>>>(
        xn, wbuf + W_SAQKV, qkv, TOK, 3 * CH, CH, nullptr, nullptr, nullptr);
    win_attn_kernel<<<NWIN * NH, 64>>>(qkv, sa_bias_t, att);
    gemm_f16_kernel<2><<<dim3(CH / BN, TOK / BM), 256, smemB>>>(
        att, wbuf + W_SAPROJ, x1, TOK, CH, CH, sa_proj_b, gamma1, x);

    // ---- stage 2: channel attention ----
    ln_row_kernel<<<lnBlocks, 256>>>(x1, ca_norm_w, ca_norm_b, xn);
    gemm_f16_kernel<0><<<dim3(3 * CH / BN, TOK / BM), 256, smemB>>>(
        xn, wbuf + W_CAQKV, qkv, TOK, 3 * CH, CH, nullptr, nullptr, nullptr);
    zero_gram_kernel<<<(NH * BATCH * HD * HD + 255) / 256, 256>>>(gram);
    ca_gram_kernel<<<dim3(NH * BATCH, 16), 576>>>(qkv, gram);
    ca_softmax_kernel<<<NH * BATCH, 32>>>(gram, Amat);
    ca_out_kernel<<<dim3(BATCH, HW / 32), 256>>>(qkv, Amat, att);
    gemm_f16_kernel<3><<<dim3(CH / BN, TOK / BM), 256, smemB>>>(
        att, wbuf + W_CAPROJ, x1, TOK, CH, CH, ca_proj_b, gamma2, x1);

    // ---- stage 3: gated FFN ----
    ln_row_kernel<<<lnBlocks, 256>>>(x1, ffn_norm_w, ffn_norm_b, xn);
    gemm_f16_kernel<1><<<dim3(FFN / BN, TOK / BM), 256, smemB>>>(
        xn, wbuf + W_FFN1, h1, TOK, FFN, CH, ffn_b1, nullptr, nullptr);
    gemm_f16_kernel<4><<<dim3(CH / BN, TOK / BM), 256, smemB>>>(
        h1, wbuf + W_FFN2, out, TOK, CH, FFN, ffn_w2b, gamma3, x1);
}

// round 15
// speedup vs baseline: 1.3425x; 1.0002x over previous
#include <cuda_runtime.h>
#include <cuda_fp16.h>
#include <math.h>
#include <stdint.h>

// ---------------------------------------------------------------------------
// Problem constants
// ---------------------------------------------------------------------------
#define BATCH 8
#define CH    192
#define HH    128
#define WW    128
#define HW    (HH*WW)            // 16384
#define TOK   (BATCH*HW)         // 131072
#define NH    8
#define HD    24
#define WS    8
#define FFN   768
#define NWIN  (BATCH*16*16)      // 2048 windows

// ---------------------------------------------------------------------------
// Scratch (device globals; no runtime allocation allowed)
// ---------------------------------------------------------------------------
__device__ __half g_xn [TOK*CH];
__device__ __half g_qkv[TOK*3*CH];
__device__ __half g_att[TOK*CH];
__device__ __half g_h1 [TOK*FFN];
__device__ float  g_x1 [TOK*CH];
__device__ float  g_gram[NH*BATCH*HD*HD];
__device__ float  g_A   [NH*BATCH*HD*HD];
// packed fp16 weights
#define W_SAQKV 0
#define W_SAPROJ (W_SAQKV + 3*CH*CH)
#define W_CAQKV (W_SAPROJ + CH*CH)
#define W_CAPROJ (W_CAQKV + 3*CH*CH)
#define W_FFN1  (W_CAPROJ + CH*CH)
#define W_FFN2  (W_FFN1 + FFN*CH)
#define W_TOTAL (W_FFN2 + CH*FFN)          // 589824
__device__ __half g_wbuf[W_TOTAL];

__device__ __forceinline__ uint32_t smem_u32(const void* p) {
    return (uint32_t)__cvta_generic_to_shared(p);
}

// ---- Blackwell packed f32x2 helpers ----
__device__ __forceinline__ unsigned long long pk2(float lo, float hi) {
    unsigned long long r;
    asm("mov.b64 %0, {%1,%2};" : "=l"(r) : "f"(lo), "f"(hi));
    return r;
}
__device__ __forceinline__ float2 upk2(unsigned long long v) {
    float2 r;
    asm("mov.b64 {%0,%1}, %2;" : "=f"(r.x), "=f"(r.y) : "l"(v));
    return r;
}
__device__ __forceinline__ unsigned long long fma2(unsigned long long a,
                                                   unsigned long long b,
                                                   unsigned long long c) {
    unsigned long long d;
    asm("fma.rn.f32x2 %0, %1, %2, %3;" : "=l"(d) : "l"(a), "l"(b), "l"(c));
    return d;
}
__device__ __forceinline__ unsigned long long mul2(unsigned long long a,
                                                   unsigned long long b) {
    unsigned long long d;
    asm("mul.rn.f32x2 %0, %1, %2;" : "=l"(d) : "l"(a), "l"(b));
    return d;
}

// ---------------------------------------------------------------------------
// Single merged fp32->fp16 conversion over all 6 weight segments
// ---------------------------------------------------------------------------
__global__ void f2h_all_kernel(const float* __restrict__ w0, const float* __restrict__ w1,
                               const float* __restrict__ w2, const float* __restrict__ w3,
                               const float* __restrict__ w4, const float* __restrict__ w5,
                               __half* __restrict__ out) {
    int i = blockIdx.x * blockDim.x + threadIdx.x;
    int e = i * 4;
    if (e >= W_TOTAL) return;
    const float* src;
    int off;
    if      (e < W_SAPROJ) { src = w0; off = e - W_SAQKV; }
    else if (e < W_CAQKV)  { src = w1; off = e - W_SAPROJ; }
    else if (e < W_CAPROJ) { src = w2; off = e - W_CAQKV; }
    else if (e < W_FFN1)   { src = w3; off = e - W_CAPROJ; }
    else if (e < W_FFN2)   { src = w4; off = e - W_FFN1; }
    else                   { src = w5; off = e - W_FFN2; }
    float4 v = *(const float4*)(src + off);
    *(__half2*)(out + e)     = __floats2half2_rn(v.x, v.y);
    *(__half2*)(out + e + 2) = __floats2half2_rn(v.z, v.w);
}

// ---------------------------------------------------------------------------
// ln_bchw: coalesced via smem transpose (R14)
// ---------------------------------------------------------------------------
#define LNT 32
__global__ __launch_bounds__(256)
void ln_bchw_kernel(const float* __restrict__ x,
                    const float* __restrict__ w,
                    const float* __restrict__ bb,
                    __half* __restrict__ out) {
    __shared__ float sx[CH][LNT + 1];
    __shared__ float smean[LNT], srstd[LNT];
    const int b  = blockIdx.y;
    const int l0 = blockIdx.x * LNT;
    const int tid = threadIdx.x;

    const float* xb = x + ((size_t)b * CH << 14) + l0;
#pragma unroll
    for (int it = 0; it < 6; it++) {
        int idx = tid + it * 256;
        int c = idx >> 3, lq = idx & 7;
        float4 v = *(const float4*)(xb + ((size_t)c << 14) + lq * 4);
        sx[c][lq * 4 + 0] = v.x;
        sx[c][lq * 4 + 1] = v.y;
        sx[c][lq * 4 + 2] = v.z;
        sx[c][lq * 4 + 3] = v.w;
    }
    __syncthreads();

    {
        int wid = tid >> 5, lane = tid & 31;
        int tok  = wid * 4 + (lane >> 3);
        int part = lane & 7;
        float s = 0.f, s2 = 0.f;
#pragma unroll
        for (int j = 0; j < 24; j++) {
            float v = sx[part + 8 * j][tok];
            s += v; s2 += v * v;
        }
#pragma unroll
        for (int o = 4; o > 0; o >>= 1) {
            s  += __shfl_xor_sync(0xffffffffu, s,  o);
            s2 += __shfl_xor_sync(0xffffffffu, s2, o);
        }
        if (part == 0) {
            float mean = s * (1.f / CH);
            float var  = s2 * (1.f / CH) - mean * mean;
            smean[tok] = mean;
            srstd[tok] = rsqrtf(var + 1e-5f);
        }
    }
    __syncthreads();

#pragma unroll
    for (int it = 0; it < 12; it++) {
        int idx = tid + it * 256;
        int tok = idx / 96, cp = idx - tok * 96;
        int c = cp * 2;
        float mean = smean[tok], rstd = srstd[tok];
        float v0 = (sx[c][tok]     - mean) * rstd * w[c]     + bb[c];
        float v1 = (sx[c + 1][tok] - mean) * rstd * w[c + 1] + bb[c + 1];
        *(__half2*)(out + (size_t)((b << 14) + l0 + tok) * CH + c) =
            __floats2half2_rn(v0, v1);
    }
}

// ---------------------------------------------------------------------------
// ln_row
// ---------------------------------------------------------------------------
__global__ void ln_row_kernel(const float* __restrict__ x,
                              const float* __restrict__ w,
                              const float* __restrict__ bb,
                              __half* __restrict__ out) {
    int gwarp = (blockIdx.x * blockDim.x + threadIdx.x) >> 5;
    int lane  = threadIdx.x & 31;
    if (gwarp >= TOK) return;
    const float* xp = x + (size_t)gwarp * CH;
    float v[6];
    float s = 0.f;
#pragma unroll
    for (int j = 0; j < 6; j++) { v[j] = xp[lane + 32 * j]; s += v[j]; }
#pragma unroll
    for (int o = 16; o > 0; o >>= 1) s += __shfl_xor_sync(0xffffffffu, s, o);
    float mean = s * (1.f / CH);
    float s2 = 0.f;
#pragma unroll
    for (int j = 0; j < 6; j++) { float d = v[j] - mean; s2 += d * d; }
#pragma unroll
    for (int o = 16; o > 0; o >>= 1) s2 += __shfl_xor_sync(0xffffffffu, s2, o);
    float rstd = rsqrtf(s2 * (1.f / CH) + 1e-5f);
    __half* op = out + (size_t)gwarp * CH;
#pragma unroll
    for (int j = 0; j < 6; j++) {
        int c = lane + 32 * j;
        op[c] = __float2half((v[j] - mean) * rstd * w[c] + bb[c]);
    }
}

// ---------------------------------------------------------------------------
// FP16 tensor-core GEMM: 128x96x32, 8 warps, 4-stage cp.async, ldmatrix
// ---------------------------------------------------------------------------
#define BM 128
#define BN 96
#define BK 32
#define STAGES 4
#define RSTRIDE 80
#define A_ST_B (BM * RSTRIDE)
#define B_ST_B (BN * RSTRIDE)
#define ST_B   (A_ST_B + B_ST_B)
#define GEMM_SMEM (STAGES * ST_B)

__device__ __forceinline__ void cp16(uint32_t dst, const void* src) {
    asm volatile("cp.async.cg.shared.global [%0], [%1], 16;" :: "r"(dst), "l"(src) : "memory");
}
__device__ __forceinline__ void ldsm4(uint32_t& r0, uint32_t& r1, uint32_t& r2, uint32_t& r3,
                                      uint32_t addr) {
    asm volatile("ldmatrix.sync.aligned.m8n8.x4.shared.b16 {%0,%1,%2,%3}, [%4];"
                 : "=r"(r0), "=r"(r1), "=r"(r2), "=r"(r3) : "r"(addr));
}

template<int MODE>
__global__ __launch_bounds__(256, 2)
void gemm_f16_kernel(const __half* __restrict__ A, const __half* __restrict__ W,
                     void* __restrict__ CoutV, int M, int N, int K,
                     const float* __restrict__ bias,
                     const float* __restrict__ gamma,
                     const float* __restrict__ resid) {
    extern __shared__ char sm[];
    const uint32_t smBase = smem_u32(sm);

    const int n0 = blockIdx.x * BN;
    const int m0 = blockIdx.y * BM;
    const int tid  = threadIdx.x;
    const int lane = tid & 31;
    const int wid  = tid >> 5;
    const int wm   = wid & 3;
    const int wn   = wid >> 2;

    float acc[2][6][4];
#pragma unroll
    for (int i = 0; i < 2; i++)
#pragma unroll
        for (int j = 0; j < 6; j++)
#pragma unroll
            for (int q = 0; q < 4; q++) acc[i][j][q] = 0.f;

    const int nK = K / BK;

    const int ldRow = tid >> 2;
    const int ldC   = tid & 3;

    auto load_stage = [&](int chunk, int st) {
        const int k0 = chunk * BK;
        const uint32_t aB = smBase + st * ST_B;
        const uint32_t bB = aB + A_ST_B;
#pragma unroll
        for (int it = 0; it < 2; it++) {
            int r = ldRow + it * 64;
            cp16(aB + r * RSTRIDE + (ldC << 4), A + (size_t)(m0 + r) * K + k0 + ldC * 8);
        }
        {
            int r = ldRow;
            cp16(bB + r * RSTRIDE + (ldC << 4), W + (size_t)(n0 + r) * K + k0 + ldC * 8);
        }
        if (tid < 128) {
            int r = 64 + ldRow;
            cp16(bB + r * RSTRIDE + (ldC << 4), W + (size_t)(n0 + r) * K + k0 + ldC * 8);
        }
        asm volatile("cp.async.commit_group;" ::: "memory");
    };

    load_stage(0, 0);
    load_stage(1, 1);
    load_stage(2, 2);

    const int seg = lane >> 3;
    const int ro  = lane & 7;
    uint32_t aOff[2];
#pragma unroll
    for (int i = 0; i < 2; i++)
        aOff[i] = (uint32_t)((wm * 32 + i * 16 + (seg & 1) * 8 + ro) * RSTRIDE
                             + ((seg >> 1) << 4));
    uint32_t bOff[3];
#pragma unroll
    for (int jp = 0; jp < 3; jp++)
        bOff[jp] = (uint32_t)(A_ST_B + (wn * 48 + jp * 16 + (seg >> 1) * 8 + ro) * RSTRIDE
                              + ((seg & 1) << 4));

    for (int kt = 0; kt < nK; kt++) {
        asm volatile("cp.async.wait_group %0;" :: "n"(STAGES - 2) : "memory");
        __syncthreads();

        if (kt + STAGES - 1 < nK) load_stage(kt + STAGES - 1, (kt + STAGES - 1) & (STAGES - 1));
        else asm volatile("cp.async.commit_group;" ::: "memory");

        const uint32_t stB = smBase + (kt & (STAGES - 1)) * ST_B;

#pragma unroll
        for (int g = 0; g < 2; g++) {
            const uint32_t gk = g * 32;
            uint32_t a[2][4];
#pragma unroll
            for (int i = 0; i < 2; i++)
                ldsm4(a[i][0], a[i][1], a[i][2], a[i][3], stB + aOff[i] + gk);
            uint32_t b[6][2];
#pragma unroll
            for (int jp = 0; jp < 3; jp++)
                ldsm4(b[jp*2][0], b[jp*2][1], b[jp*2+1][0], b[jp*2+1][1], stB + bOff[jp] + gk);
#pragma unroll
            for (int i = 0; i < 2; i++)
#pragma unroll
                for (int j = 0; j < 6; j++) {
                    asm volatile(
                        "mma.sync.aligned.m16n8k16.row.col.f32.f16.f16.f32 "
                        "{%0,%1,%2,%3},{%4,%5,%6,%7},{%8,%9},{%0,%1,%2,%3};"
                        : "+f"(acc[i][j][0]), "+f"(acc[i][j][1]),
                          "+f"(acc[i][j][2]), "+f"(acc[i][j][3])
                        : "r"(a[i][0]), "r"(a[i][1]), "r"(a[i][2]), "r"(a[i][3]),
                          "r"(b[j][0]), "r"(b[j][1]));
                }
        }
        __syncthreads();
    }

    const int rq = lane >> 2;
    const int cq = (lane & 3) * 2;
    __half* Ch = (__half*)CoutV;
    float*  Cf = (float*)CoutV;
#pragma unroll
    for (int i = 0; i < 2; i++) {
#pragma unroll
        for (int j = 0; j < 6; j++) {
#pragma unroll
            for (int half_ = 0; half_ < 2; half_++) {
                int m = m0 + wm * 32 + i * 16 + rq + half_ * 8;
                int n = n0 + wn * 48 + j * 8 + cq;
                float v0 = acc[i][j][half_ * 2 + 0];
                float v1 = acc[i][j][half_ * 2 + 1];
                if (MODE == 0) {
                    *(__half2*)(Ch + (size_t)m * N + n) = __floats2half2_rn(v0, v1);
                } else if (MODE == 1) {
                    v0 += bias[n];     v1 += bias[n + 1];
                    v0 = 0.5f * v0 * (1.0f + erff(v0 * 0.70710678118654752f));
                    v1 = 0.5f * v1 * (1.0f + erff(v1 * 0.70710678118654752f));
                    *(__half2*)(Ch + (size_t)m * N + n) = __floats2half2_rn(v0, v1);
                } else if (MODE == 2) {
                    int bb_ = m >> 14, l = m & (HW - 1);
                    float r0 = resid[((size_t)(bb_ * CH + n)     << 14) + l];
                    float r1 = resid[((size_t)(bb_ * CH + n + 1) << 14) + l];
                    float2 o;
                    o.x = r0 + gamma[n]     * (v0 + bias[n]);
                    o.y = r1 + gamma[n + 1] * (v1 + bias[n + 1]);
                    *(float2*)(Cf + (size_t)m * N + n) = o;
                } else if (MODE == 3) {
                    float2 rr = *(const float2*)(resid + (size_t)m * N + n);
                    float2 o;
                    o.x = rr.x + gamma[n]     * (v0 + bias[n]);
                    o.y = rr.y + gamma[n + 1] * (v1 + bias[n + 1]);
                    *(float2*)(Cf + (size_t)m * N + n) = o;
                } else { // MODE 4
                    int bb_ = m >> 14, l = m & (HW - 1);
                    float r0 = resid[(size_t)m * N + n];
                    float r1 = resid[(size_t)m * N + n + 1];
                    Cf[((size_t)(bb_ * CH + n)     << 14) + l] = r0 + gamma[n]     * (v0 + bias[n]);
                    Cf[((size_t)(bb_ * CH + n + 1) << 14) + l] = r1 + gamma[n + 1] * (v1 + bias[n + 1]);
                }
            }
        }
    }
}

// ---------------------------------------------------------------------------
// Window attention v4: 32-thread blocks, 2 queries per lane (i, i+32);
// k/v row loaded once per j, shared by both queries. Online softmax,
// packed f32x2 FMA for dot and accumulate.
// ---------------------------------------------------------------------------
__global__ __launch_bounds__(32)
void win_attn_kernel(const __half* __restrict__ qkv,
                     const float* __restrict__ table,
                     __half* __restrict__ out) {
    int h   = blockIdx.x & 7;
    int wid = blockIdx.x >> 3;
    int b   = wid >> 8;
    int rem = wid & 255;
    int wy  = rem >> 4, wx = rem & 15;

    int lane = threadIdx.x;           // 0..31

    __shared__ float ks[64][24];      // 16B-aligned rows (96B)
    __shared__ float vs[64][24];
    __shared__ float bt[240];
    for (int p = lane; p < 225; p += 32) bt[p] = table[p * NH + h];

    unsigned long long qp[2][12];
    int tok[2], iyq[2], ixq;
    ixq = lane & 7;
#pragma unroll
    for (int s = 0; s < 2; s++) {
        int i = lane + 32 * s;
        int iy = i >> 3, ix = i & 7;
        iyq[s] = iy;
        int t = (b << 14) + ((wy * 8 + iy) << 7) + wx * 8 + ix;
        tok[s] = t;
        const uint4* rowp = (const uint4*)(qkv + (size_t)t * (3 * CH) + h * HD);
#pragma unroll
        for (int c4 = 0; c4 < 3; c4++) {
            uint4 qv = rowp[c4];
            uint4 kv = rowp[c4 + CH / 8];
            uint4 vv = rowp[c4 + 2 * CH / 8];
            const __half2* qh = (const __half2*)&qv;
            const __half2* kh = (const __half2*)&kv;
            const __half2* vh = (const __half2*)&vv;
#pragma unroll
            for (int p = 0; p < 4; p++) {
                float2 qf = __half22float2(qh[p]);
                float2 kf = __half22float2(kh[p]);
                float2 vf = __half22float2(vh[p]);
                qp[s][c4 * 4 + p] = pk2(qf.x, qf.y);
                ks[i][c4 * 8 + p * 2]     = kf.x;
                ks[i][c4 * 8 + p * 2 + 1] = kf.y;
                vs[i][c4 * 8 + p * 2]     = vf.x;
                vs[i][c4 * 8 + p * 2 + 1] = vf.y;
            }
        }
    }
    __syncthreads();

    const float scale = 0.20412414523193154f;
    float mx0 = -1e30f, sum0 = 0.f;
    float mx1 = -1e30f, sum1 = 0.f;
    unsigned long long ap0[12], ap1[12];
#pragma unroll
    for (int d = 0; d < 12; d++) { ap0[d] = 0ull; ap1[d] = 0ull; }

#pragma unroll 2
    for (int j = 0; j < 64; j++) {
        int jy = j >> 3, jx = j & 7;
        const double* kr = (const double*)&ks[j][0];
        unsigned long long dp0 = 0ull, dp1 = 0ull;
#pragma unroll
        for (int d = 0; d < 12; d++) {
            unsigned long long kk = __double_as_longlong(kr[d]);
            dp0 = fma2(kk, qp[0][d], dp0);
            dp1 = fma2(kk, qp[1][d], dp1);
        }
        float2 d0 = upk2(dp0), d1 = upk2(dp1);
        int bcol = (ixq - jx + 7);
        float dot0 = (d0.x + d0.y) * scale + bt[(iyq[0] - jy + 7) * 15 + bcol];
        float dot1 = (d1.x + d1.y) * scale + bt[(iyq[1] - jy + 7) * 15 + bcol];

        if (dot0 > mx0) {
            float rs = __expf(mx0 - dot0);
            sum0 *= rs;
            unsigned long long rp = pk2(rs, rs);
#pragma unroll
            for (int d = 0; d < 12; d++) ap0[d] = mul2(ap0[d], rp);
            mx0 = dot0;
        }
        if (dot1 > mx1) {
            float rs = __expf(mx1 - dot1);
            sum1 *= rs;
            unsigned long long rp = pk2(rs, rs);
#pragma unroll
            for (int d = 0; d < 12; d++) ap1[d] = mul2(ap1[d], rp);
            mx1 = dot1;
        }
        float p0 = __expf(dot0 - mx0);
        float p1 = __expf(dot1 - mx1);
        sum0 += p0;
        sum1 += p1;
        unsigned long long pp0 = pk2(p0, p0);
        unsigned long long pp1 = pk2(p1, p1);
        const double* vr = (const double*)&vs[j][0];
#pragma unroll
        for (int d = 0; d < 12; d++) {
            unsigned long long vv = __double_as_longlong(vr[d]);
            ap0[d] = fma2(pp0, vv, ap0[d]);
            ap1[d] = fma2(pp1, vv, ap1[d]);
        }
    }

#pragma unroll
    for (int s = 0; s < 2; s++) {
        float inv = (s == 0) ? (1.f / sum0) : (1.f / sum1);
        unsigned long long* ap = (s == 0) ? ap0 : ap1;
        __half* op = out + (size_t)tok[s] * CH + h * HD;
        uint4 ov[3];
        __half2* oh = (__half2*)ov;
#pragma unroll
        for (int d = 0; d < 12; d++) {
            float2 a = upk2(ap[d]);
            oh[d] = __floats2half2_rn(a.x * inv, a.y * inv);
        }
        uint4* op4 = (uint4*)op;
#pragma unroll
        for (int c4 = 0; c4 < 3; c4++) op4[c4] = ov[c4];
    }
}

// ---------------------------------------------------------------------------
// Channel attention
// ---------------------------------------------------------------------------
__global__ __launch_bounds__(576)
void ca_gram_kernel(const __half* __restrict__ qkv, float* __restrict__ gram) {
    int bh = blockIdx.x;
    int b = bh >> 3, h = bh & 7;
    int tid = threadIdx.x;
    int d = tid / 24, e = tid - d * 24;

    __shared__ float qs[64][24];
    __shared__ float ks[64][24];

    const int chunk = HW / 16;
    int l0 = blockIdx.y * chunk;
    float accum = 0.f;
    for (int tile = 0; tile < chunk; tile += 64) {
        for (int p = tid; p < 64 * 24; p += 576) {
            int tok = p / 24, dd = p - tok * 24;
            size_t base = (size_t)((b << 14) + l0 + tile + tok) * (3 * CH) + h * HD + dd;
            qs[tok][dd] = __half2float(qkv[base]);
            ks[tok][dd] = __half2float(qkv[base + CH]);
        }
        __syncthreads();
#pragma unroll 8
        for (int tok = 0; tok < 64; tok++) accum += qs[tok][d] * ks[tok][e];
        __syncthreads();
    }
    atomicAdd(&gram[bh * (HD * HD) + tid], accum);
}

__global__ void zero_gram_kernel(float* __restrict__ gram) {
    int i = blockIdx.x * blockDim.x + threadIdx.x;
    if (i < NH * BATCH * HD * HD) gram[i] = 0.f;
}

__global__ void ca_softmax_kernel(const float* __restrict__ gram, float* __restrict__ A) {
    int bh = blockIdx.x;
    int d = threadIdx.x;
    if (d >= HD) return;
    const float scale = 0.20412414523193154f;
    float r[24];
    float mx = -1e30f;
#pragma unroll
    for (int e = 0; e < HD; e++) {
        r[e] = gram[bh * (HD * HD) + d * HD + e] * scale;
        mx = fmaxf(mx, r[e]);
    }
    float sum = 0.f;
#pragma unroll
    for (int e = 0; e < HD; e++) { r[e] = __expf(r[e] - mx); sum += r[e]; }
    float inv = 1.f / sum;
#pragma unroll
    for (int e = 0; e < HD; e++) A[bh * (HD * HD) + d * HD + e] = r[e] * inv;
}

__global__ __launch_bounds__(256)
void ca_out_kernel(const __half* __restrict__ qkv, const float* __restrict__ A,
                   __half* __restrict__ out) {
    int b  = blockIdx.x;
    int l0 = blockIdx.y * 32;
    int tid = threadIdx.x;
    __shared__ float vs[32][192];
    for (int p = tid; p < 32 * 192; p += 256) {
        int tok = p / 192, c = p - tok * 192;
        vs[tok][c] = __half2float(qkv[(size_t)((b << 14) + l0 + tok) * (3 * CH) + 2 * CH + c]);
    }
    __syncthreads();
    int tok = tid >> 3;
    int h   = tid & 7;
    int t   = (b << 14) + l0 + tok;
    const float* Ah = A + (b * 8 + h) * (HD * HD);
    __half* op = out + (size_t)t * CH + h * HD;
#pragma unroll
    for (int d = 0; d < HD; d++) {
        float s = 0.f;
#pragma unroll
        for (int e = 0; e < HD; e++) s += Ah[d * HD + e] * vs[tok][h * HD + e];
        op[d] = __float2half(s);
    }
}

// ---------------------------------------------------------------------------
// Launch
// ---------------------------------------------------------------------------
extern "C" void kernel_launch(void* const* d_in, const int* in_sizes, int n_in,
                              void* d_out, int out_size) {
    const float* x          = (const float*)d_in[0];
    const float* sa_norm_w  = (const float*)d_in[1];
    const float* sa_norm_b  = (const float*)d_in[2];
    const float* sa_qkv_w   = (const float*)d_in[3];
    const float* sa_proj_w  = (const float*)d_in[4];
    const float* sa_proj_b  = (const float*)d_in[5];
    const float* sa_bias_t  = (const float*)d_in[6];
    const float* ca_norm_w  = (const float*)d_in[7];
    const float* ca_norm_b  = (const float*)d_in[8];
    const float* ca_qkv_w   = (const float*)d_in[9];
    const float* ca_proj_w  = (const float*)d_in[10];
    const float* ca_proj_b  = (const float*)d_in[11];
    const float* ffn_norm_w = (const float*)d_in[12];
    const float* ffn_norm_b = (const float*)d_in[13];
    const float* ffn_w1     = (const float*)d_in[14];
    const float* ffn_b1     = (const float*)d_in[15];
    const float* ffn_w2     = (const float*)d_in[16];
    const float* ffn_w2b    = (const float*)d_in[17];
    const float* gamma1     = (const float*)d_in[18];
    const float* gamma2     = (const float*)d_in[19];
    const float* gamma3     = (const float*)d_in[20];
    float* out = (float*)d_out;

    __half *xn, *qkv, *att, *h1, *wbuf;
    float *x1, *gram, *Amat;
    cudaGetSymbolAddress((void**)&xn,   g_xn);
    cudaGetSymbolAddress((void**)&qkv,  g_qkv);
    cudaGetSymbolAddress((void**)&att,  g_att);
    cudaGetSymbolAddress((void**)&h1,   g_h1);
    cudaGetSymbolAddress((void**)&x1,   g_x1);
    cudaGetSymbolAddress((void**)&gram, g_gram);
    cudaGetSymbolAddress((void**)&Amat, g_A);
    cudaGetSymbolAddress((void**)&wbuf, g_wbuf);

    const int smemB = GEMM_SMEM;  // 71680
    cudaFuncSetAttribute(gemm_f16_kernel<0>, cudaFuncAttributeMaxDynamicSharedMemorySize, smemB);
    cudaFuncSetAttribute(gemm_f16_kernel<1>, cudaFuncAttributeMaxDynamicSharedMemorySize, smemB);
    cudaFuncSetAttribute(gemm_f16_kernel<2>, cudaFuncAttributeMaxDynamicSharedMemorySize, smemB);
    cudaFuncSetAttribute(gemm_f16_kernel<3>, cudaFuncAttributeMaxDynamicSharedMemorySize, smemB);
    cudaFuncSetAttribute(gemm_f16_kernel<4>, cudaFuncAttributeMaxDynamicSharedMemorySize, smemB);

    f2h_all_kernel<<<(W_TOTAL / 4 + 255) / 256, 256>>>(
        sa_qkv_w, sa_proj_w, ca_qkv_w, ca_proj_w, ffn_w1, ffn_w2, wbuf);

    const int lnBlocks = TOK / 8;

    // ---- stage 1: window attention ----
    ln_bchw_kernel<<<dim3(HW / LNT, BATCH), 256>>>(x, sa_norm_w, sa_norm_b, xn);
    gemm_f16_kernel<0><<<dim3(3 * CH / BN, TOK / BM), 256, smemB>>>(
        xn, wbuf + W_SAQKV, qkv, TOK, 3 * CH, CH, nullptr, nullptr, nullptr);
    win_attn_kernel<<<NWIN * NH, 32>>>(qkv, sa_bias_t, att);
    gemm_f16_kernel<2><<<dim3(CH / BN, TOK / BM), 256, smemB>>>(
        att, wbuf + W_SAPROJ, x1, TOK, CH, CH, sa_proj_b, gamma1, x);

    // ---- stage 2: channel attention ----
    ln_row_kernel<<<lnBlocks, 256>>>(x1, ca_norm_w, ca_norm_b, xn);
    gemm_f16_kernel<0><<<dim3(3 * CH / BN, TOK / BM), 256, smemB>>>(
        xn, wbuf + W_CAQKV, qkv, TOK, 3 * CH, CH, nullptr, nullptr, nullptr);
    zero_gram_kernel<<<(NH * BATCH * HD * HD + 255) / 256, 256>>>(gram);
    ca_gram_kernel<<<dim3(NH * BATCH, 16), 576>>>(qkv, gram);
    ca_softmax_kernel<<<NH * BATCH, 32>>>(gram, Amat);
    ca_out_kernel<<<dim3(BATCH, HW / 32), 256>>>(qkv, Amat, att);
    gemm_f16_kernel<3><<<dim3(CH / BN, TOK / BM), 256, smemB>>>(
        att, wbuf + W_CAPROJ, x1, TOK, CH, CH, ca_proj_b, gamma2, x1);

    // ---- stage 3: gated FFN ----
    ln_row_kernel<<<lnBlocks, 256>>>(x1, ffn_norm_w, ffn_norm_b, xn);
    gemm_f16_kernel<1><<<dim3(FFN / BN, TOK / BM), 256, smemB>>>(
        xn, wbuf + W_FFN1, h1, TOK, FFN, CH, ffn_b1, nullptr, nullptr);
    gemm_f16_kernel<4><<<dim3(CH / BN, TOK / BM), 256, smemB>>>(
        h1, wbuf + W_FFN2, out, TOK, CH, FFN, ffn_w2b, gamma3, x1);
}